// round 10
// baseline (speedup 1.0000x reference)
#include <cuda_runtime.h>
#include <cuda_fp16.h>
#include <cstdint>

#define T_SEQ 128
#define NBATCH 2048
#define HDIM  128
#define GDIM  384
#define XDIM  38
#define TB    16

// ---------------- device scratch ----------------
__device__ float   g_gi[(size_t)T_SEQ * NBATCH * GDIM];
__device__ float   g_hall[(size_t)NBATCH * T_SEQ * HDIM];  // [b][t][j]
__device__ float   g_h0[(size_t)NBATCH * HDIM];
__device__ float   g_h1[(size_t)NBATCH * HDIM];
__device__ float4  g_dWhh4[32 * GDIM];
__device__ float   g_Wrz_rm[256 * HDIM];
__device__ float   g_Wcn_rm[128 * HDIM];
__device__ float   g_bcomb[GDIM];
__device__ float   g_brz[256];

__device__ __forceinline__ float sigf(float x)  { return __fdividef(1.f, 1.f + __expf(-x)); }
__device__ __forceinline__ float tanhf_(float x){ return __fdividef(2.f, 1.f + __expf(-2.f * x)) - 1.f; }

__device__ __forceinline__ uint32_t smem_u32(const void* p) {
    uint32_t a;
    asm("{ .reg .u64 t; cvta.to.shared.u64 t, %1; cvt.u32.u64 %0, t; }" : "=r"(a) : "l"(p));
    return a;
}

#define LDSM4(r, a) \
    asm volatile("ldmatrix.sync.aligned.m8n8.x4.shared.b16 {%0,%1,%2,%3}, [%4];" \
        : "=r"((r)[0]), "=r"((r)[1]), "=r"((r)[2]), "=r"((r)[3]) : "r"(a))

#define MMA16816(d, a, b0, b1) \
    asm volatile("mma.sync.aligned.m16n8k16.row.col.f32.f16.f16.f32 " \
        "{%0,%1,%2,%3}, {%4,%5,%6,%7}, {%8,%9}, {%0,%1,%2,%3};" \
        : "+f"((d)[0]), "+f"((d)[1]), "+f"((d)[2]), "+f"((d)[3]) \
        : "r"((a)[0]), "r"((a)[1]), "r"((a)[2]), "r"((a)[3]), "r"(b0), "r"(b1))

#define WSTR 272
#define GSTR 17

// enc smem map
#define E_W   0              // 384*272
#define E_G   104448         // 384*17*4
#define E_BHI 130560         // 16*272
#define E_BLO 134912
#define E_SZ  139264
// dec smem map
#define D_W   0              // 512*272
#define D_G   139264         // 512*17*4
#define D_BHI 174080
#define D_BLO 178432
#define D_SZ  182784

// ---------------- weight prep ----------------
__global__ void prep_kernel(const float* __restrict__ dWhh,
                            const float* __restrict__ dWih, const float* __restrict__ linW,
                            const float* __restrict__ linb, const float* __restrict__ dbih,
                            const float* __restrict__ dbhh)
{
    int g = blockIdx.x * 128 + threadIdx.x;
    if (g >= GDIM) return;

    for (int kc = 0; kc < 32; ++kc) {
        const float* d = dWhh + g * HDIM + kc * 4;
        g_dWhh4[kc * GDIM + g] = make_float4(d[0], d[1], d[2], d[3]);
    }

    float wih[XDIM];
#pragma unroll
    for (int p = 0; p < XDIM; ++p) wih[p] = dWih[g * XDIM + p];

    float bc = dbih[g];
#pragma unroll
    for (int p = 0; p < XDIM; ++p) bc = fmaf(wih[p], linb[p], bc);
    g_bcomb[g] = bc;
    if (g < 256) g_brz[g] = bc + dbhh[g];

    for (int kc = 0; kc < 32; ++kc) {
        float a4[4] = {0.f, 0.f, 0.f, 0.f};
#pragma unroll
        for (int p = 0; p < XDIM; ++p) {
            float wv = wih[p];
            const float* lp = linW + p * HDIM + kc * 4;
            a4[0] = fmaf(wv, lp[0], a4[0]);
            a4[1] = fmaf(wv, lp[1], a4[1]);
            a4[2] = fmaf(wv, lp[2], a4[2]);
            a4[3] = fmaf(wv, lp[3], a4[3]);
        }
        if (g < 256) {
            const float* d = dWhh + g * HDIM + kc * 4;
#pragma unroll
            for (int n = 0; n < 4; ++n) g_Wrz_rm[g * HDIM + kc * 4 + n] = a4[n] + d[n];
        } else {
#pragma unroll
            for (int n = 0; n < 4; ++n) g_Wcn_rm[(g - 256) * HDIM + kc * 4 + n] = a4[n];
        }
    }
}

// ---------------- gi = x @ enc_Wih^T + enc_bih ----------------
__global__ __launch_bounds__(384) void gi_kernel(const float* __restrict__ x,
                                                 const float* __restrict__ wih,
                                                 const float* __restrict__ bih)
{
    __shared__ float xs[32 * XDIM];
    int tid = threadIdx.x;
    int r0  = blockIdx.x * 32;
    for (int i = tid; i < 32 * XDIM; i += 384) xs[i] = x[(size_t)r0 * XDIM + i];
    __syncthreads();

    float w[XDIM];
#pragma unroll
    for (int p = 0; p < XDIM; ++p) w[p] = wih[tid * XDIM + p];
    float bias = bih[tid];

    for (int b = 0; b < 32; ++b) {
        float acc = bias;
#pragma unroll
        for (int p = 0; p < XDIM; ++p) acc = fmaf(xs[b * XDIM + p], w[p], acc);
        int row = r0 + b;
        g_gi[((size_t)(row & 127) * NBATCH + (row >> 7)) * GDIM + tid] = acc;
    }
}

// stage fp16 W (row-major src) into smem (stride 272B)
__device__ __forceinline__ void stage_w(char* smem, const float* src, int row, int k) {
    *(__half*)(smem + row * WSTR + k * 2) = __float2half_rn(src[k]);
}
// write h hi/lo fp16 tiles at (c, j)
__device__ __forceinline__ void put_h(char* smem, uint32_t obhi, uint32_t oblo,
                                      int c, int j, float hv) {
    __half hb = __float2half_rn(hv);
    *(__half*)(smem + obhi + c * WSTR + j * 2) = hb;
    *(__half*)(smem + oblo + c * WSTR + j * 2) = __float2half_rn(hv - __half2float(hb));
}

// ---------------- encoder recurrence (fp16 2-pass, split-group pipelined) ----------------
__global__ __launch_bounds__(512, 1) void enc_tc_kernel(const float* __restrict__ eWhh,
                                                        const float* __restrict__ bhh)
{
    extern __shared__ char smem[];
    uint32_t sb = smem_u32(smem);
    int tid = threadIdx.x, wid = tid >> 5, lane = tid & 31;
    int b0 = blockIdx.x * TB;
    float* Gf = (float*)(smem + E_G);

    for (int i = tid; i < GDIM * HDIM; i += 512)
        stage_w(smem + E_W, eWhh + (i >> 7) * HDIM, i >> 7, i & 127);
    for (int i = tid; i < TB * HDIM; i += 512) {
        int c = i >> 7, j = i & 127;
        *(__half*)(smem + E_BHI + c * WSTR + j * 2) = __float2half_rn(0.f);
        *(__half*)(smem + E_BLO + c * WSTR + j * 2) = __float2half_rn(0.f);
    }
    __syncthreads();

    uint32_t whi[2][8][4];
    uint32_t baseA = sb + E_W + (wid * 32 + (lane & 15)) * WSTR + (lane >> 4) * 16;
    if (wid < 12) {
#pragma unroll
        for (int m = 0; m < 2; ++m)
#pragma unroll
            for (int kc = 0; kc < 8; ++kc)
                LDSM4(whi[m][kc], baseA + m * 16 * WSTR + kc * 32);
    }

    int jj = tid & 127, cb = (tid >> 7) * 2;
    float bh_r = bhh[jj], bh_z = bhh[jj + 128], bh_n = bhh[jj + 256];
    uint32_t baseBh = sb + E_BHI + (lane & 7) * WSTR + (lane >> 3) * 16;
    uint32_t baseBl = sb + E_BLO + (lane & 7) * WSTR + (lane >> 3) * 16;
    int gq = lane >> 2, tig = lane & 3;
    float hreg[2][2] = {{0.f, 0.f}, {0.f, 0.f}};
    float pAr[2], pAz[2], pAn[2], pBr[2], pBz[2], pBn[2];

#define ENC_MMA(g)                                                                   \
    do {                                                                             \
        float d[2][4];                                                               \
        for (int m = 0; m < 2; ++m)                                                  \
            for (int q = 0; q < 4; ++q) d[m][q] = 0.f;                               \
        uint32_t goff = (g) * 8 * WSTR;                                              \
        _Pragma("unroll")                                                            \
        for (int kp = 0; kp < 4; ++kp) {                                             \
            uint32_t bhv[4], blv[4];                                                 \
            LDSM4(bhv, baseBh + goff + kp * 64);                                     \
            LDSM4(blv, baseBl + goff + kp * 64);                                     \
            _Pragma("unroll")                                                        \
            for (int ch = 0; ch < 2; ++ch) {                                         \
                int kc = kp * 2 + ch;                                                \
                _Pragma("unroll")                                                    \
                for (int m = 0; m < 2; ++m) {                                        \
                    MMA16816(d[m], whi[m][kc], bhv[2 * ch], bhv[2 * ch + 1]);        \
                    MMA16816(d[m], whi[m][kc], blv[2 * ch], blv[2 * ch + 1]);        \
                }                                                                    \
            }                                                                        \
        }                                                                            \
        _Pragma("unroll")                                                            \
        for (int m = 0; m < 2; ++m) {                                                \
            int row = wid * 32 + m * 16 + gq;                                        \
            int col = (g) * 8 + 2 * tig;                                             \
            Gf[row * GSTR + col]           = d[m][0];                                \
            Gf[row * GSTR + col + 1]       = d[m][1];                                \
            Gf[(row + 8) * GSTR + col]     = d[m][2];                                \
            Gf[(row + 8) * GSTR + col + 1] = d[m][3];                                \
        }                                                                            \
    } while (0)

#define ENC_PREF(g, t, pr, pz, pn)                                                   \
    do {                                                                             \
        const float* gp = g_gi + ((size_t)(t) * NBATCH + b0) * GDIM;                 \
        _Pragma("unroll")                                                            \
        for (int i = 0; i < 2; ++i) {                                                \
            int c = (g) * 8 + cb + i;                                                \
            pr[i] = gp[c * GDIM + jj];                                               \
            pz[i] = gp[c * GDIM + 128 + jj];                                         \
            pn[i] = gp[c * GDIM + 256 + jj];                                         \
        }                                                                            \
    } while (0)

#define ENC_EPI(g, pr, pz, pn)                                                       \
    do {                                                                             \
        _Pragma("unroll")                                                            \
        for (int i = 0; i < 2; ++i) {                                                \
            int c = (g) * 8 + cb + i;                                                \
            float r = sigf(pr[i] + bh_r + Gf[jj * GSTR + c]);                        \
            float z = sigf(pz[i] + bh_z + Gf[(128 + jj) * GSTR + c]);                \
            float n = tanhf_(pn[i] + r * (Gf[(256 + jj) * GSTR + c] + bh_n));        \
            float h = hreg[g][i];                                                    \
            float hv = n + z * (h - n);                                              \
            hreg[g][i] = hv;                                                         \
            put_h(smem, E_BHI, E_BLO, c, jj, hv);                                    \
        }                                                                            \
    } while (0)

    ENC_PREF(0, 0, pAr, pAz, pAn);
    __syncthreads();
    if (wid < 12) ENC_MMA(0);
    __syncthreads();

    for (int t = 0; t < T_SEQ; ++t) {
        ENC_PREF(1, t, pBr, pBz, pBn);
        if (wid < 12) ENC_MMA(1);
        ENC_EPI(0, pAr, pAz, pAn);
        __syncthreads();
        if (t + 1 < T_SEQ) {
            ENC_PREF(0, t + 1, pAr, pAz, pAn);
            if (wid < 12) ENC_MMA(0);
        }
        ENC_EPI(1, pBr, pBz, pBn);
        __syncthreads();
    }

#pragma unroll
    for (int g = 0; g < 2; ++g)
#pragma unroll
        for (int i = 0; i < 2; ++i) {
            int c = g * 8 + cb + i;
            g_h0[(size_t)(b0 + c) * HDIM + jj] = hreg[g][i];
        }
}

// ---------------- decoder t=0 (plain FFMA) ----------------
__global__ __launch_bounds__(512, 1) void dec0_kernel(const float* __restrict__ dbih,
                                                      const float* __restrict__ dbhh)
{
    __shared__ float4 hs4[TB * 32];
    float* hs = (float*)hs4;
    int tid = threadIdx.x;
    int j = tid & 127, s = tid >> 7;
    int b0 = blockIdx.x * TB;

    for (int i = tid; i < TB * HDIM; i += 512) hs[i] = g_h0[(size_t)b0 * HDIM + i];
    float bi_r = dbih[j], bi_z = dbih[j + 128], bi_n = dbih[j + 256];
    __syncthreads();

    float ar[4] = {0, 0, 0, 0}, az[4] = {0, 0, 0, 0}, an[4] = {0, 0, 0, 0};
#pragma unroll 4
    for (int kc = 0; kc < 32; ++kc) {
        float4 wr = g_dWhh4[kc * GDIM + j];
        float4 wz = g_dWhh4[kc * GDIM + 128 + j];
        float4 wn = g_dWhh4[kc * GDIM + 256 + j];
#pragma unroll
        for (int nn = 0; nn < 4; ++nn) {
            float4 hv = hs4[(s + nn * 4) * 32 + kc];
            ar[nn] = fmaf(hv.x, wr.x, ar[nn]); ar[nn] = fmaf(hv.y, wr.y, ar[nn]);
            ar[nn] = fmaf(hv.z, wr.z, ar[nn]); ar[nn] = fmaf(hv.w, wr.w, ar[nn]);
            az[nn] = fmaf(hv.x, wz.x, az[nn]); az[nn] = fmaf(hv.y, wz.y, az[nn]);
            az[nn] = fmaf(hv.z, wz.z, az[nn]); az[nn] = fmaf(hv.w, wz.w, az[nn]);
            an[nn] = fmaf(hv.x, wn.x, an[nn]); an[nn] = fmaf(hv.y, wn.y, an[nn]);
            an[nn] = fmaf(hv.z, wn.z, an[nn]); an[nn] = fmaf(hv.w, wn.w, an[nn]);
        }
    }
    float bh_r = dbhh[j], bh_z = dbhh[j + 128], bh_n = dbhh[j + 256];
#pragma unroll
    for (int nn = 0; nn < 4; ++nn) {
        int b = s + nn * 4;
        float r = sigf(bi_r + bh_r + ar[nn]);
        float z = sigf(bi_z + bh_z + az[nn]);
        float n = tanhf_(bi_n + r * (an[nn] + bh_n));
        float h = hs[b * HDIM + j];
        float hv = n + z * (h - n);
        g_hall[((size_t)(b0 + b) * T_SEQ + 0) * HDIM + j] = hv;
        g_h1[(size_t)(b0 + b) * HDIM + j] = hv;
    }
}

// ---------------- decoder recurrence t=1..127 (fp16 2-pass, pipelined) ----------------
__global__ __launch_bounds__(512, 1) void dec_tc_kernel(const float* __restrict__ dWhh,
                                                        const float* __restrict__ dbhh)
{
    extern __shared__ char smem[];
    uint32_t sb = smem_u32(smem);
    int tid = threadIdx.x, wid = tid >> 5, lane = tid & 31;
    int b0 = blockIdx.x * TB;
    float* Gf = (float*)(smem + D_G);

    for (int i = tid; i < 512 * HDIM; i += 512) {
        int row = i >> 7, k = i & 127;
        const float* src = (row < 256) ? (g_Wrz_rm + (size_t)row * HDIM)
                        : (row < 384) ? (dWhh + (size_t)row * HDIM)
                                      : (g_Wcn_rm + (size_t)(row - 384) * HDIM);
        stage_w(smem + D_W, src, row, k);
    }
    __syncthreads();

    uint32_t whi[2][8][4];
    uint32_t baseA = sb + D_W + (wid * 32 + (lane & 15)) * WSTR + (lane >> 4) * 16;
#pragma unroll
    for (int m = 0; m < 2; ++m)
#pragma unroll
        for (int kc = 0; kc < 8; ++kc)
            LDSM4(whi[m][kc], baseA + m * 16 * WSTR + kc * 32);

    int jj = tid & 127, cb = (tid >> 7) * 2;
    float hreg[2][2];
#pragma unroll
    for (int g = 0; g < 2; ++g)
#pragma unroll
        for (int i = 0; i < 2; ++i) {
            int c = g * 8 + cb + i;
            float hv = g_h1[(size_t)(b0 + c) * HDIM + jj];
            hreg[g][i] = hv;
            put_h(smem, D_BHI, D_BLO, c, jj, hv);
        }

    float brz_r = g_brz[jj], brz_z = g_brz[jj + 128];
    float bcn = g_bcomb[jj + 256], bh_n = dbhh[jj + 256];
    uint32_t baseBh = sb + D_BHI + (lane & 7) * WSTR + (lane >> 3) * 16;
    uint32_t baseBl = sb + D_BLO + (lane & 7) * WSTR + (lane >> 3) * 16;
    int gq = lane >> 2, tig = lane & 3;

#define DEC_MMA(g)                                                                   \
    do {                                                                             \
        float d[2][4];                                                               \
        for (int m = 0; m < 2; ++m)                                                  \
            for (int q = 0; q < 4; ++q) d[m][q] = 0.f;                               \
        uint32_t goff = (g) * 8 * WSTR;                                              \
        _Pragma("unroll")                                                            \
        for (int kp = 0; kp < 4; ++kp) {                                             \
            uint32_t bhv[4], blv[4];                                                 \
            LDSM4(bhv, baseBh + goff + kp * 64);                                     \
            LDSM4(blv, baseBl + goff + kp * 64);                                     \
            _Pragma("unroll")                                                        \
            for (int ch = 0; ch < 2; ++ch) {                                         \
                int kc = kp * 2 + ch;                                                \
                _Pragma("unroll")                                                    \
                for (int m = 0; m < 2; ++m) {                                        \
                    MMA16816(d[m], whi[m][kc], bhv[2 * ch], bhv[2 * ch + 1]);        \
                    MMA16816(d[m], whi[m][kc], blv[2 * ch], blv[2 * ch + 1]);        \
                }                                                                    \
            }                                                                        \
        }                                                                            \
        _Pragma("unroll")                                                            \
        for (int m = 0; m < 2; ++m) {                                                \
            int row = wid * 32 + m * 16 + gq;                                        \
            int col = (g) * 8 + 2 * tig;                                             \
            Gf[row * GSTR + col]           = d[m][0];                                \
            Gf[row * GSTR + col + 1]       = d[m][1];                                \
            Gf[(row + 8) * GSTR + col]     = d[m][2];                                \
            Gf[(row + 8) * GSTR + col + 1] = d[m][3];                                \
        }                                                                            \
    } while (0)

#define DEC_EPI(g, tt)                                                               \
    do {                                                                             \
        _Pragma("unroll")                                                            \
        for (int i = 0; i < 2; ++i) {                                                \
            int c = (g) * 8 + cb + i;                                                \
            float r = sigf(brz_r + Gf[jj * GSTR + c]);                               \
            float z = sigf(brz_z + Gf[(128 + jj) * GSTR + c]);                       \
            float n = tanhf_(bcn + Gf[(384 + jj) * GSTR + c]                         \
                             + r * (Gf[(256 + jj) * GSTR + c] + bh_n));              \
            float h = hreg[g][i];                                                    \
            float hv = n + z * (h - n);                                              \
            hreg[g][i] = hv;                                                         \
            g_hall[((size_t)(b0 + c) * T_SEQ + (tt) + 1) * HDIM + jj] = hv;          \
            put_h(smem, D_BHI, D_BLO, c, jj, hv);                                    \
        }                                                                            \
    } while (0)

    __syncthreads();
    DEC_MMA(0);
    __syncthreads();

    for (int tt = 0; tt < T_SEQ - 1; ++tt) {
        DEC_MMA(1);
        DEC_EPI(0, tt);
        __syncthreads();
        if (tt + 1 < T_SEQ - 1) DEC_MMA(0);
        DEC_EPI(1, tt);
        __syncthreads();
    }
}

// ---------------- out = g_hall @ lin_W^T + lin_b ----------------
__global__ void out_kernel(const float* __restrict__ linW, const float* __restrict__ linb,
                           float* __restrict__ out)
{
    __shared__ float hS[16 * HDIM];
    __shared__ float lS[HDIM * XDIM];
    int tx = threadIdx.x, ty = threadIdx.y;
    int tid = ty * XDIM + tx;
    int nthr = XDIM * 16;
    size_t r0 = (size_t)blockIdx.x * 16;

    for (int i = tid; i < 16 * HDIM; i += nthr) hS[i] = g_hall[r0 * HDIM + i];
    for (int i = tid; i < HDIM * XDIM; i += nthr) {
        int k = i / XDIM, p = i - k * XDIM;
        lS[i] = linW[p * HDIM + k];
    }
    __syncthreads();

    float acc = linb[tx];
    const float* hrow = hS + ty * HDIM;
#pragma unroll 8
    for (int k = 0; k < HDIM; ++k) acc = fmaf(hrow[k], lS[k * XDIM + tx], acc);
    out[(r0 + ty) * XDIM + tx] = acc;
}

// ---------------- launch ----------------
extern "C" void kernel_launch(void* const* d_in, const int* in_sizes, int n_in,
                              void* d_out, int out_size) {
    const float* x        = (const float*)d_in[0];
    const float* enc_Wih  = (const float*)d_in[1];
    const float* enc_Whh  = (const float*)d_in[2];
    const float* enc_bih  = (const float*)d_in[3];
    const float* enc_bhh  = (const float*)d_in[4];
    const float* dec_Wih  = (const float*)d_in[5];
    const float* dec_Whh  = (const float*)d_in[6];
    const float* dec_bih  = (const float*)d_in[7];
    const float* dec_bhh  = (const float*)d_in[8];
    const float* lin_W    = (const float*)d_in[9];
    const float* lin_b    = (const float*)d_in[10];
    float* out = (float*)d_out;

    cudaFuncSetAttribute(enc_tc_kernel, cudaFuncAttributeMaxDynamicSharedMemorySize, E_SZ);
    cudaFuncSetAttribute(dec_tc_kernel, cudaFuncAttributeMaxDynamicSharedMemorySize, D_SZ);

    prep_kernel<<<3, 128>>>(dec_Whh, dec_Wih, lin_W, lin_b, dec_bih, dec_bhh);
    gi_kernel<<<(T_SEQ * NBATCH) / 32, 384>>>(x, enc_Wih, enc_bih);
    enc_tc_kernel<<<NBATCH / TB, 512, E_SZ>>>(enc_Whh, enc_bhh);
    dec0_kernel<<<NBATCH / TB, 512>>>(dec_bih, dec_bhh);
    dec_tc_kernel<<<NBATCH / TB, 512, D_SZ>>>(dec_Whh, dec_bhh);
    out_kernel<<<(NBATCH * T_SEQ) / 16, dim3(XDIM, 16)>>>(lin_W, lin_b, out);
}

// round 12
// speedup vs baseline: 1.1187x; 1.1187x over previous
#include <cuda_runtime.h>
#include <cuda_fp16.h>
#include <cstdint>

#define T_SEQ 128
#define NBATCH 2048
#define HDIM  128
#define GDIM  384
#define XDIM  38
#define TB    16

// ---------------- device scratch ----------------
__device__ float   g_gi[(size_t)T_SEQ * NBATCH * GDIM];
__device__ float   g_hall[(size_t)NBATCH * T_SEQ * HDIM];  // [b][t][j]
__device__ float   g_h0[(size_t)NBATCH * HDIM];
__device__ float   g_h1[(size_t)NBATCH * HDIM];
__device__ float4  g_dWhh4[32 * GDIM];
__device__ float   g_Wrz_rm[256 * HDIM];
__device__ float   g_Wcn_rm[128 * HDIM];
__device__ float   g_bcomb[GDIM];
__device__ float   g_brz[256];

__device__ __forceinline__ float sigf(float x)  { return __fdividef(1.f, 1.f + __expf(-x)); }
__device__ __forceinline__ float tanhf_(float x){ return __fdividef(2.f, 1.f + __expf(-2.f * x)) - 1.f; }

__device__ __forceinline__ uint32_t smem_u32(const void* p) {
    uint32_t a;
    asm("{ .reg .u64 t; cvta.to.shared.u64 t, %1; cvt.u32.u64 %0, t; }" : "=r"(a) : "l"(p));
    return a;
}

#define LDSM4(r, a) \
    asm volatile("ldmatrix.sync.aligned.m8n8.x4.shared.b16 {%0,%1,%2,%3}, [%4];" \
        : "=r"((r)[0]), "=r"((r)[1]), "=r"((r)[2]), "=r"((r)[3]) : "r"(a))

#define MMA16816(d, a, b0, b1) \
    asm volatile("mma.sync.aligned.m16n8k16.row.col.f32.f16.f16.f32 " \
        "{%0,%1,%2,%3}, {%4,%5,%6,%7}, {%8,%9}, {%0,%1,%2,%3};" \
        : "+f"((d)[0]), "+f"((d)[1]), "+f"((d)[2]), "+f"((d)[3]) \
        : "r"((a)[0]), "r"((a)[1]), "r"((a)[2]), "r"((a)[3]), "r"(b0), "r"(b1))

#define WSTR 272

// shared smem map for both recurrence kernels: 512 permuted W rows + 2 B buffers
#define SM_W  0
#define SM_B0 139264          // 512*272
#define SM_B1 143616          // + 16*272
#define SM_SZ 147968          // + 16*272

// ---------------- weight prep ----------------
__global__ void prep_kernel(const float* __restrict__ dWhh,
                            const float* __restrict__ dWih, const float* __restrict__ linW,
                            const float* __restrict__ linb, const float* __restrict__ dbih,
                            const float* __restrict__ dbhh)
{
    int g = blockIdx.x * 128 + threadIdx.x;
    if (g >= GDIM) return;

    for (int kc = 0; kc < 32; ++kc) {
        const float* d = dWhh + g * HDIM + kc * 4;
        g_dWhh4[kc * GDIM + g] = make_float4(d[0], d[1], d[2], d[3]);
    }

    float wih[XDIM];
#pragma unroll
    for (int p = 0; p < XDIM; ++p) wih[p] = dWih[g * XDIM + p];

    float bc = dbih[g];
#pragma unroll
    for (int p = 0; p < XDIM; ++p) bc = fmaf(wih[p], linb[p], bc);
    g_bcomb[g] = bc;
    if (g < 256) g_brz[g] = bc + dbhh[g];

    for (int kc = 0; kc < 32; ++kc) {
        float a4[4] = {0.f, 0.f, 0.f, 0.f};
#pragma unroll
        for (int p = 0; p < XDIM; ++p) {
            float wv = wih[p];
            const float* lp = linW + p * HDIM + kc * 4;
            a4[0] = fmaf(wv, lp[0], a4[0]);
            a4[1] = fmaf(wv, lp[1], a4[1]);
            a4[2] = fmaf(wv, lp[2], a4[2]);
            a4[3] = fmaf(wv, lp[3], a4[3]);
        }
        if (g < 256) {
            const float* d = dWhh + g * HDIM + kc * 4;
#pragma unroll
            for (int n = 0; n < 4; ++n) g_Wrz_rm[g * HDIM + kc * 4 + n] = a4[n] + d[n];
        } else {
#pragma unroll
            for (int n = 0; n < 4; ++n) g_Wcn_rm[(g - 256) * HDIM + kc * 4 + n] = a4[n];
        }
    }
}

// ---------------- gi = x @ enc_Wih^T + enc_bih ----------------
__global__ __launch_bounds__(384) void gi_kernel(const float* __restrict__ x,
                                                 const float* __restrict__ wih,
                                                 const float* __restrict__ bih)
{
    __shared__ float xs[32 * XDIM];
    int tid = threadIdx.x;
    int r0  = blockIdx.x * 32;
    for (int i = tid; i < 32 * XDIM; i += 384) xs[i] = x[(size_t)r0 * XDIM + i];
    __syncthreads();

    float w[XDIM];
#pragma unroll
    for (int p = 0; p < XDIM; ++p) w[p] = wih[tid * XDIM + p];
    float bias = bih[tid];

    for (int b = 0; b < 32; ++b) {
        float acc = bias;
#pragma unroll
        for (int p = 0; p < XDIM; ++p) acc = fmaf(xs[b * XDIM + p], w[p], acc);
        int row = r0 + b;
        g_gi[((size_t)(row & 127) * NBATCH + (row >> 7)) * GDIM + tid] = acc;
    }
}

// ---------------- encoder recurrence: register-epilogue fp16 mma ----------------
// physical row layout, warp w (16 warps): rows 32w..32w+31 =
//   [r_{8w..8w+7} | z_{8w..8w+7} | n_{8w..8w+7} | pad(zeros)]
__global__ __launch_bounds__(512, 1) void enc_tc_kernel(const float* __restrict__ eWhh,
                                                        const float* __restrict__ bhh)
{
    extern __shared__ char smem[];
    uint32_t sb = smem_u32(smem);
    int tid = threadIdx.x, wid = tid >> 5, lane = tid & 31;
    int b0 = blockIdx.x * TB;

    // stage permuted fp16 W
    for (int idx = tid; idx < 512 * HDIM; idx += 512) {
        int p = idx >> 7, k = idx & 127;
        int w = p >> 5, q = p & 31, jr = 8 * w + (q & 7), gt = q >> 3;
        float v = (gt == 0) ? eWhh[(size_t)jr * HDIM + k]
                : (gt == 1) ? eWhh[(size_t)(128 + jr) * HDIM + k]
                : (gt == 2) ? eWhh[(size_t)(256 + jr) * HDIM + k] : 0.f;
        *(__half*)(smem + SM_W + p * WSTR + k * 2) = __float2half_rn(v);
    }
    // zero B buf0
    for (int i = tid; i < TB * HDIM; i += 512) {
        int c = i >> 7, j = i & 127;
        *(__half*)(smem + SM_B0 + c * WSTR + j * 2) = __float2half_rn(0.f);
    }
    __syncthreads();

    // resident W fragments
    uint32_t whi[2][8][4];
    uint32_t baseA = sb + SM_W + (wid * 32 + (lane & 15)) * WSTR + (lane >> 4) * 16;
#pragma unroll
    for (int m = 0; m < 2; ++m)
#pragma unroll
        for (int kc = 0; kc < 8; ++kc)
            LDSM4(whi[m][kc], baseA + m * 16 * WSTR + kc * 32);

    int gq = lane >> 2, tig = lane & 3;
    int j = 8 * wid + gq;
    float br = bhh[j], bz = bhh[128 + j], bn = bhh[256 + j];
    int cv[4] = {2 * tig, 2 * tig + 1, 8 + 2 * tig, 9 + 2 * tig};
    float hreg[4] = {0.f, 0.f, 0.f, 0.f};
    uint32_t bB[2] = {sb + SM_B0 + (lane & 7) * WSTR + (lane >> 3) * 16,
                      sb + SM_B1 + (lane & 7) * WSTR + (lane >> 3) * 16};

    for (int t = 0; t < T_SEQ; ++t) {
        int cur = t & 1;
        char* stbuf = smem + (cur ? SM_B0 : SM_B1) + j * 2;   // next buffer, generic ptr
        // prefetch gi
        const float* gp = g_gi + ((size_t)t * NBATCH + b0) * GDIM;
        float gr[4], gz[4], gn[4];
#pragma unroll
        for (int i = 0; i < 4; ++i) {
            int c = cv[i];
            gr[i] = gp[c * GDIM + j];
            gz[i] = gp[c * GDIM + 128 + j];
            gn[i] = gp[c * GDIM + 256 + j];
        }

        float d[2][2][4];
#pragma unroll
        for (int m = 0; m < 2; ++m)
#pragma unroll
            for (int n = 0; n < 2; ++n)
#pragma unroll
                for (int q = 0; q < 4; ++q) d[m][n][q] = 0.f;

#pragma unroll
        for (int kp = 0; kp < 4; ++kp) {
            uint32_t b0v[4], b1v[4];
            LDSM4(b0v, bB[cur] + kp * 64);
            LDSM4(b1v, bB[cur] + 8 * WSTR + kp * 64);
#pragma unroll
            for (int ch = 0; ch < 2; ++ch) {
                int kc = kp * 2 + ch;
#pragma unroll
                for (int m = 0; m < 2; ++m) {
                    MMA16816(d[m][0], whi[m][kc], b0v[2 * ch], b0v[2 * ch + 1]);
                    MMA16816(d[m][1], whi[m][kc], b1v[2 * ch], b1v[2 * ch + 1]);
                }
            }
        }

        // register epilogue
#pragma unroll
        for (int i = 0; i < 4; ++i) {
            int n = i >> 1, lo = i & 1, c = cv[i];
            float r = sigf(gr[i] + br + d[0][n][lo]);
            float z = sigf(gz[i] + bz + d[0][n][2 + lo]);
            float nn = tanhf_(gn[i] + r * (d[1][n][lo] + bn));
            float hv = nn + z * (hreg[i] - nn);
            hreg[i] = hv;
            *(__half*)(stbuf + c * WSTR) = __float2half_rn(hv);
        }
        __syncthreads();
    }

#pragma unroll
    for (int i = 0; i < 4; ++i)
        g_h0[(size_t)(b0 + cv[i]) * HDIM + j] = hreg[i];
}

// ---------------- decoder t=0 (plain FFMA) ----------------
__global__ __launch_bounds__(512, 1) void dec0_kernel(const float* __restrict__ dbih,
                                                      const float* __restrict__ dbhh)
{
    __shared__ float4 hs4[TB * 32];
    float* hs = (float*)hs4;
    int tid = threadIdx.x;
    int j = tid & 127, s = tid >> 7;
    int b0 = blockIdx.x * TB;

    for (int i = tid; i < TB * HDIM; i += 512) hs[i] = g_h0[(size_t)b0 * HDIM + i];
    float bi_r = dbih[j], bi_z = dbih[j + 128], bi_n = dbih[j + 256];
    __syncthreads();

    float ar[4] = {0, 0, 0, 0}, az[4] = {0, 0, 0, 0}, an[4] = {0, 0, 0, 0};
#pragma unroll 4
    for (int kc = 0; kc < 32; ++kc) {
        float4 wr = g_dWhh4[kc * GDIM + j];
        float4 wz = g_dWhh4[kc * GDIM + 128 + j];
        float4 wn = g_dWhh4[kc * GDIM + 256 + j];
#pragma unroll
        for (int nn = 0; nn < 4; ++nn) {
            float4 hv = hs4[(s + nn * 4) * 32 + kc];
            ar[nn] = fmaf(hv.x, wr.x, ar[nn]); ar[nn] = fmaf(hv.y, wr.y, ar[nn]);
            ar[nn] = fmaf(hv.z, wr.z, ar[nn]); ar[nn] = fmaf(hv.w, wr.w, ar[nn]);
            az[nn] = fmaf(hv.x, wz.x, az[nn]); az[nn] = fmaf(hv.y, wz.y, az[nn]);
            az[nn] = fmaf(hv.z, wz.z, az[nn]); az[nn] = fmaf(hv.w, wz.w, az[nn]);
            an[nn] = fmaf(hv.x, wn.x, an[nn]); an[nn] = fmaf(hv.y, wn.y, an[nn]);
            an[nn] = fmaf(hv.z, wn.z, an[nn]); an[nn] = fmaf(hv.w, wn.w, an[nn]);
        }
    }
    float bh_r = dbhh[j], bh_z = dbhh[j + 128], bh_n = dbhh[j + 256];
#pragma unroll
    for (int nn = 0; nn < 4; ++nn) {
        int b = s + nn * 4;
        float r = sigf(bi_r + bh_r + ar[nn]);
        float z = sigf(bi_z + bh_z + az[nn]);
        float n = tanhf_(bi_n + r * (an[nn] + bh_n));
        float h = hs[b * HDIM + j];
        float hv = n + z * (h - n);
        g_hall[((size_t)(b0 + b) * T_SEQ + 0) * HDIM + j] = hv;
        g_h1[(size_t)(b0 + b) * HDIM + j] = hv;
    }
}

// ---------------- decoder recurrence t=1..127: register-epilogue fp16 mma ----------------
// warp w rows: [rz_r_{8w..}|rz_z|whh_n|wcn], j = 8w+gq
__global__ __launch_bounds__(512, 1) void dec_tc_kernel(const float* __restrict__ dWhh,
                                                        const float* __restrict__ dbhh)
{
    extern __shared__ char smem[];
    uint32_t sb = smem_u32(smem);
    int tid = threadIdx.x, wid = tid >> 5, lane = tid & 31;
    int b0 = blockIdx.x * TB;

    // stage permuted fp16 W
    for (int idx = tid; idx < 512 * HDIM; idx += 512) {
        int p = idx >> 7, k = idx & 127;
        int w = p >> 5, q = p & 31, jr = 8 * w + (q & 7), gt = q >> 3;
        float v = (gt == 0) ? g_Wrz_rm[(size_t)jr * HDIM + k]
                : (gt == 1) ? g_Wrz_rm[(size_t)(128 + jr) * HDIM + k]
                : (gt == 2) ? dWhh[(size_t)(256 + jr) * HDIM + k]
                            : g_Wcn_rm[(size_t)jr * HDIM + k];
        *(__half*)(smem + SM_W + p * WSTR + k * 2) = __float2half_rn(v);
    }
    __syncthreads();

    uint32_t whi[2][8][4];
    uint32_t baseA = sb + SM_W + (wid * 32 + (lane & 15)) * WSTR + (lane >> 4) * 16;
#pragma unroll
    for (int m = 0; m < 2; ++m)
#pragma unroll
        for (int kc = 0; kc < 8; ++kc)
            LDSM4(whi[m][kc], baseA + m * 16 * WSTR + kc * 32);

    int gq = lane >> 2, tig = lane & 3;
    int j = 8 * wid + gq;
    float brz_r = g_brz[j], brz_z = g_brz[128 + j];
    float bcn = g_bcomb[256 + j], bh_n = dbhh[256 + j];
    int cv[4] = {2 * tig, 2 * tig + 1, 8 + 2 * tig, 9 + 2 * tig};
    uint32_t bB[2] = {sb + SM_B0 + (lane & 7) * WSTR + (lane >> 3) * 16,
                      sb + SM_B1 + (lane & 7) * WSTR + (lane >> 3) * 16};

    // init h from g_h1 into regs + B buf0
    float hreg[4];
#pragma unroll
    for (int i = 0; i < 4; ++i) {
        int c = cv[i];
        float hv = g_h1[(size_t)(b0 + c) * HDIM + j];
        hreg[i] = hv;
        *(__half*)(smem + SM_B0 + c * WSTR + j * 2) = __float2half_rn(hv);
    }
    __syncthreads();

    for (int tt = 0; tt < T_SEQ - 1; ++tt) {
        int cur = tt & 1;
        char* stbuf = smem + (cur ? SM_B0 : SM_B1) + j * 2;   // next buffer, generic ptr
        float d[2][2][4];
#pragma unroll
        for (int m = 0; m < 2; ++m)
#pragma unroll
            for (int n = 0; n < 2; ++n)
#pragma unroll
                for (int q = 0; q < 4; ++q) d[m][n][q] = 0.f;

#pragma unroll
        for (int kp = 0; kp < 4; ++kp) {
            uint32_t b0v[4], b1v[4];
            LDSM4(b0v, bB[cur] + kp * 64);
            LDSM4(b1v, bB[cur] + 8 * WSTR + kp * 64);
#pragma unroll
            for (int ch = 0; ch < 2; ++ch) {
                int kc = kp * 2 + ch;
#pragma unroll
                for (int m = 0; m < 2; ++m) {
                    MMA16816(d[m][0], whi[m][kc], b0v[2 * ch], b0v[2 * ch + 1]);
                    MMA16816(d[m][1], whi[m][kc], b1v[2 * ch], b1v[2 * ch + 1]);
                }
            }
        }

#pragma unroll
        for (int i = 0; i < 4; ++i) {
            int n = i >> 1, lo = i & 1, c = cv[i];
            float r = sigf(brz_r + d[0][n][lo]);
            float z = sigf(brz_z + d[0][n][2 + lo]);
            float nn = tanhf_(bcn + d[1][n][2 + lo] + r * (d[1][n][lo] + bh_n));
            float hv = nn + z * (hreg[i] - nn);
            hreg[i] = hv;
            g_hall[((size_t)(b0 + c) * T_SEQ + tt + 1) * HDIM + j] = hv;
            *(__half*)(stbuf + c * WSTR) = __float2half_rn(hv);
        }
        __syncthreads();
    }
}

// ---------------- out = g_hall @ lin_W^T + lin_b ----------------
__global__ void out_kernel(const float* __restrict__ linW, const float* __restrict__ linb,
                           float* __restrict__ out)
{
    __shared__ float hS[16 * HDIM];
    __shared__ float lS[HDIM * XDIM];
    int tx = threadIdx.x, ty = threadIdx.y;
    int tid = ty * XDIM + tx;
    int nthr = XDIM * 16;
    size_t r0 = (size_t)blockIdx.x * 16;

    for (int i = tid; i < 16 * HDIM; i += nthr) hS[i] = g_hall[r0 * HDIM + i];
    for (int i = tid; i < HDIM * XDIM; i += nthr) {
        int k = i / XDIM, p = i - k * XDIM;
        lS[i] = linW[p * HDIM + k];
    }
    __syncthreads();

    float acc = linb[tx];
    const float* hrow = hS + ty * HDIM;
#pragma unroll 8
    for (int k = 0; k < HDIM; ++k) acc = fmaf(hrow[k], lS[k * XDIM + tx], acc);
    out[(r0 + ty) * XDIM + tx] = acc;
}

// ---------------- launch ----------------
extern "C" void kernel_launch(void* const* d_in, const int* in_sizes, int n_in,
                              void* d_out, int out_size) {
    const float* x        = (const float*)d_in[0];
    const float* enc_Wih  = (const float*)d_in[1];
    const float* enc_Whh  = (const float*)d_in[2];
    const float* enc_bih  = (const float*)d_in[3];
    const float* enc_bhh  = (const float*)d_in[4];
    const float* dec_Wih  = (const float*)d_in[5];
    const float* dec_Whh  = (const float*)d_in[6];
    const float* dec_bih  = (const float*)d_in[7];
    const float* dec_bhh  = (const float*)d_in[8];
    const float* lin_W    = (const float*)d_in[9];
    const float* lin_b    = (const float*)d_in[10];
    float* out = (float*)d_out;

    cudaFuncSetAttribute(enc_tc_kernel, cudaFuncAttributeMaxDynamicSharedMemorySize, SM_SZ);
    cudaFuncSetAttribute(dec_tc_kernel, cudaFuncAttributeMaxDynamicSharedMemorySize, SM_SZ);

    prep_kernel<<<3, 128>>>(dec_Whh, dec_Wih, lin_W, lin_b, dec_bih, dec_bhh);
    gi_kernel<<<(T_SEQ * NBATCH) / 32, 384>>>(x, enc_Wih, enc_bih);
    enc_tc_kernel<<<NBATCH / TB, 512, SM_SZ>>>(enc_Whh, enc_bhh);
    dec0_kernel<<<NBATCH / TB, 512>>>(dec_bih, dec_bhh);
    dec_tc_kernel<<<NBATCH / TB, 512, SM_SZ>>>(dec_Whh, dec_bhh);
    out_kernel<<<(NBATCH * T_SEQ) / 16, dim3(XDIM, 16)>>>(lin_W, lin_b, out);
}

// round 13
// speedup vs baseline: 1.5920x; 1.4230x over previous
#include <cuda_runtime.h>
#include <cuda_fp16.h>
#include <cstdint>

#define T_SEQ 128
#define NBATCH 2048
#define HDIM  128
#define GDIM  384
#define XDIM  38
#define TB    16

// ---------------- device scratch ----------------
__device__ float   g_hall[(size_t)NBATCH * T_SEQ * HDIM];  // [b][t][j]
__device__ float   g_h0[(size_t)NBATCH * HDIM];
__device__ float   g_h1[(size_t)NBATCH * HDIM];
__device__ float4  g_dWhh4[32 * GDIM];
__device__ float   g_Wrz_rm[256 * HDIM];
__device__ float   g_Wcn_rm[128 * HDIM];
__device__ float   g_bcomb[GDIM];
__device__ float   g_brz[256];

__device__ __forceinline__ float sigf(float x)  { return __fdividef(1.f, 1.f + __expf(-x)); }
__device__ __forceinline__ float tanhf_(float x){ return __fdividef(2.f, 1.f + __expf(-2.f * x)) - 1.f; }

__device__ __forceinline__ uint32_t smem_u32(const void* p) {
    uint32_t a;
    asm("{ .reg .u64 t; cvta.to.shared.u64 t, %1; cvt.u32.u64 %0, t; }" : "=r"(a) : "l"(p));
    return a;
}

#define LDSM4(r, a) \
    asm volatile("ldmatrix.sync.aligned.m8n8.x4.shared.b16 {%0,%1,%2,%3}, [%4];" \
        : "=r"((r)[0]), "=r"((r)[1]), "=r"((r)[2]), "=r"((r)[3]) : "r"(a))

#define MMA16816(d, a, b0, b1) \
    asm volatile("mma.sync.aligned.m16n8k16.row.col.f32.f16.f16.f32 " \
        "{%0,%1,%2,%3}, {%4,%5,%6,%7}, {%8,%9}, {%0,%1,%2,%3};" \
        : "+f"((d)[0]), "+f"((d)[1]), "+f"((d)[2]), "+f"((d)[3]) \
        : "r"((a)[0]), "r"((a)[1]), "r"((a)[2]), "r"((a)[3]), "r"(b0), "r"(b1))

#define WSTR 272

// ---- enc smem map: Whh + Wih + h double-buf + x double-buf ----
#define EW   0                 // 512*272 = 139264
#define EWX  139264            // 512*112 = 57344
#define EHB0 196608            // 16*272
#define EHB1 200960
#define EXB0 205312
#define EXB1 209664
#define E_SZ 214016
// ---- dec smem map ----
#define D_W  0                 // 512*272
#define D_B0 139264
#define D_B1 143616
#define D_SZ 147968

// ---------------- weight prep ----------------
__global__ void prep_kernel(const float* __restrict__ dWhh,
                            const float* __restrict__ dWih, const float* __restrict__ linW,
                            const float* __restrict__ linb, const float* __restrict__ dbih,
                            const float* __restrict__ dbhh)
{
    int g = blockIdx.x * 128 + threadIdx.x;
    if (g >= GDIM) return;

    for (int kc = 0; kc < 32; ++kc) {
        const float* d = dWhh + g * HDIM + kc * 4;
        g_dWhh4[kc * GDIM + g] = make_float4(d[0], d[1], d[2], d[3]);
    }

    float wih[XDIM];
#pragma unroll
    for (int p = 0; p < XDIM; ++p) wih[p] = dWih[g * XDIM + p];

    float bc = dbih[g];
#pragma unroll
    for (int p = 0; p < XDIM; ++p) bc = fmaf(wih[p], linb[p], bc);
    g_bcomb[g] = bc;
    if (g < 256) g_brz[g] = bc + dbhh[g];

    for (int kc = 0; kc < 32; ++kc) {
        float a4[4] = {0.f, 0.f, 0.f, 0.f};
#pragma unroll
        for (int p = 0; p < XDIM; ++p) {
            float wv = wih[p];
            const float* lp = linW + p * HDIM + kc * 4;
            a4[0] = fmaf(wv, lp[0], a4[0]);
            a4[1] = fmaf(wv, lp[1], a4[1]);
            a4[2] = fmaf(wv, lp[2], a4[2]);
            a4[3] = fmaf(wv, lp[3], a4[3]);
        }
        if (g < 256) {
            const float* d = dWhh + g * HDIM + kc * 4;
#pragma unroll
            for (int n = 0; n < 4; ++n) g_Wrz_rm[g * HDIM + kc * 4 + n] = a4[n] + d[n];
        } else {
#pragma unroll
            for (int n = 0; n < 4; ++n) g_Wcn_rm[(g - 256) * HDIM + kc * 4 + n] = a4[n];
        }
    }
}

// ---------------- encoder: fused x-projection + recurrence, register epilogue ----------------
// Whh rows (warp w): [r_{8w..8w+7} | z | n | pad]; Wih rows: [r | z | zeros | n]
__global__ __launch_bounds__(512, 1) void enc_tc_kernel(
    const float* __restrict__ x,
    const float* __restrict__ eWhh, const float* __restrict__ eWih,
    const float* __restrict__ ebih, const float* __restrict__ ebhh)
{
    extern __shared__ char smem[];
    uint32_t sb = smem_u32(smem);
    int tid = threadIdx.x, wid = tid >> 5, lane = tid & 31;
    int b0 = blockIdx.x * TB;

    // stage permuted Whh (stride 272)
    for (int idx = tid; idx < 512 * HDIM; idx += 512) {
        int p = idx >> 7, k = idx & 127;
        int w = p >> 5, q = p & 31, jr = 8 * w + (q & 7), gt = q >> 3;
        float v = (gt == 0) ? eWhh[(size_t)jr * HDIM + k]
                : (gt == 1) ? eWhh[(size_t)(128 + jr) * HDIM + k]
                : (gt == 2) ? eWhh[(size_t)(256 + jr) * HDIM + k] : 0.f;
        *(__half*)(smem + EW + p * WSTR + k * 2) = __float2half_rn(v);
    }
    // stage permuted Wih (48 cols, stride 112); m1 layout = [zeros | Wih_n]
    for (int idx = tid; idx < 512 * 48; idx += 512) {
        int p = idx / 48, k = idx - p * 48;
        int w = p >> 5, q = p & 31, jr = 8 * w + (q & 7), gt = q >> 3;
        float v = 0.f;
        if (k < XDIM)
            v = (gt == 0) ? eWih[(size_t)jr * XDIM + k]
              : (gt == 1) ? eWih[(size_t)(128 + jr) * XDIM + k]
              : (gt == 3) ? eWih[(size_t)(256 + jr) * XDIM + k] : 0.f;
        *(__half*)(smem + EWX + p * 112 + k * 2) = __float2half_rn(v);
    }
    // zero h buf0 and both x buffers (16 rows x 64 cols each)
    for (int i = tid; i < TB * HDIM; i += 512) {
        int c = i >> 7, j = i & 127;
        *(__half*)(smem + EHB0 + c * WSTR + j * 2) = __float2half_rn(0.f);
    }
    for (int i = tid; i < 2 * TB * 64; i += 512) {
        int buf = i >> 10, c = (i >> 6) & 15, k = i & 63;
        *(__half*)(smem + (buf ? EXB1 : EXB0) + c * WSTR + k * 2) = __float2half_rn(0.f);
    }
    // stage x(t=0) into XB0
    for (int v = tid; v < TB * XDIM; v += 512) {
        int c = v / XDIM, k = v - c * XDIM;
        *(__half*)(smem + EXB0 + c * WSTR + k * 2) =
            __float2half_rn(x[((size_t)(b0 + c) * T_SEQ + 0) * XDIM + k]);
    }
    __syncthreads();

    // resident Whh fragments
    uint32_t whi[2][8][4];
    uint32_t baseA  = sb + EW  + (wid * 32 + (lane & 15)) * WSTR + (lane >> 4) * 16;
    uint32_t baseAX = sb + EWX + (wid * 32 + (lane & 15)) * 112  + (lane >> 4) * 16;
#pragma unroll
    for (int m = 0; m < 2; ++m)
#pragma unroll
        for (int kc = 0; kc < 8; ++kc)
            LDSM4(whi[m][kc], baseA + m * 16 * WSTR + kc * 32);

    int gq = lane >> 2, tig = lane & 3;
    int j = 8 * wid + gq;
    float br = ebih[j] + ebhh[j];
    float bz = ebih[128 + j] + ebhh[128 + j];
    float bin = ebih[256 + j], bhn = ebhh[256 + j];
    int cv[4] = {2 * tig, 2 * tig + 1, 8 + 2 * tig, 9 + 2 * tig};
    float hreg[4] = {0.f, 0.f, 0.f, 0.f};
    uint32_t hB[2] = {sb + EHB0 + (lane & 7) * WSTR + (lane >> 3) * 16,
                      sb + EHB1 + (lane & 7) * WSTR + (lane >> 3) * 16};
    uint32_t xB[2] = {sb + EXB0 + (lane & 7) * WSTR + (lane >> 3) * 16,
                      sb + EXB1 + (lane & 7) * WSTR + (lane >> 3) * 16};
    // x prefetch/store indices (time-invariant)
    int c0x = tid / XDIM, k0x = tid - c0x * XDIM;
    int v1 = tid + 512;
    int c1x = v1 / XDIM, k1x = v1 - c1x * XDIM;
    bool has1 = (v1 < TB * XDIM);

    for (int t = 0; t < T_SEQ; ++t) {
        int cur = t & 1;
        // prefetch x(t+1) from global (hidden under mma)
        float xp0 = 0.f, xp1 = 0.f;
        if (t + 1 < T_SEQ) {
            xp0 = x[((size_t)(b0 + c0x) * T_SEQ + t + 1) * XDIM + k0x];
            if (has1) xp1 = x[((size_t)(b0 + c1x) * T_SEQ + t + 1) * XDIM + k1x];
        }

        float d[2][2][4];
#pragma unroll
        for (int m = 0; m < 2; ++m)
#pragma unroll
            for (int n = 0; n < 2; ++n)
#pragma unroll
                for (int q = 0; q < 4; ++q) d[m][n][q] = 0.f;

        // h-recurrence mma (K=128)
#pragma unroll
        for (int kp = 0; kp < 4; ++kp) {
            uint32_t b0v[4], b1v[4];
            LDSM4(b0v, hB[cur] + kp * 64);
            LDSM4(b1v, hB[cur] + 8 * WSTR + kp * 64);
#pragma unroll
            for (int ch = 0; ch < 2; ++ch) {
                int kc = kp * 2 + ch;
#pragma unroll
                for (int m = 0; m < 2; ++m) {
                    MMA16816(d[m][0], whi[m][kc], b0v[2 * ch], b0v[2 * ch + 1]);
                    MMA16816(d[m][1], whi[m][kc], b1v[2 * ch], b1v[2 * ch + 1]);
                }
            }
        }
        // x-projection mma (K=48: kc 0..2)
#pragma unroll
        for (int kp = 0; kp < 2; ++kp) {
            uint32_t x0v[4], x1v[4];
            LDSM4(x0v, xB[cur] + kp * 64);
            LDSM4(x1v, xB[cur] + 8 * WSTR + kp * 64);
#pragma unroll
            for (int ch = 0; ch < 2; ++ch) {
                int kc = kp * 2 + ch;
                if (kc < 3) {
                    uint32_t a0[4], a1[4];
                    LDSM4(a0, baseAX + kc * 32);
                    LDSM4(a1, baseAX + 16 * 112 + kc * 32);
                    MMA16816(d[0][0], a0, x0v[2 * ch], x0v[2 * ch + 1]);
                    MMA16816(d[0][1], a0, x1v[2 * ch], x1v[2 * ch + 1]);
                    MMA16816(d[1][0], a1, x0v[2 * ch], x0v[2 * ch + 1]);
                    MMA16816(d[1][1], a1, x1v[2 * ch], x1v[2 * ch + 1]);
                }
            }
        }

        // register epilogue (gi already in d)
        char* sth = smem + (cur ? EHB0 : EHB1) + j * 2;
#pragma unroll
        for (int i = 0; i < 4; ++i) {
            int nn = i >> 1, lo = i & 1, c = cv[i];
            float r = sigf(br + d[0][nn][lo]);
            float z = sigf(bz + d[0][nn][2 + lo]);
            float n = tanhf_(bin + d[1][nn][2 + lo] + r * (d[1][nn][lo] + bhn));
            float hv = n + z * (hreg[i] - n);
            hreg[i] = hv;
            *(__half*)(sth + c * WSTR) = __float2half_rn(hv);
        }
        // store x(t+1) into next x buffer
        if (t + 1 < T_SEQ) {
            char* stx = smem + (cur ? EXB0 : EXB1);
            *(__half*)(stx + c0x * WSTR + k0x * 2) = __float2half_rn(xp0);
            if (has1) *(__half*)(stx + c1x * WSTR + k1x * 2) = __float2half_rn(xp1);
        }
        __syncthreads();
    }

#pragma unroll
    for (int i = 0; i < 4; ++i)
        g_h0[(size_t)(b0 + cv[i]) * HDIM + j] = hreg[i];
}

// ---------------- decoder t=0 (plain FFMA) ----------------
__global__ __launch_bounds__(512, 1) void dec0_kernel(const float* __restrict__ dbih,
                                                      const float* __restrict__ dbhh)
{
    __shared__ float4 hs4[TB * 32];
    float* hs = (float*)hs4;
    int tid = threadIdx.x;
    int j = tid & 127, s = tid >> 7;
    int b0 = blockIdx.x * TB;

    for (int i = tid; i < TB * HDIM; i += 512) hs[i] = g_h0[(size_t)b0 * HDIM + i];
    float bi_r = dbih[j], bi_z = dbih[j + 128], bi_n = dbih[j + 256];
    __syncthreads();

    float ar[4] = {0, 0, 0, 0}, az[4] = {0, 0, 0, 0}, an[4] = {0, 0, 0, 0};
#pragma unroll 4
    for (int kc = 0; kc < 32; ++kc) {
        float4 wr = g_dWhh4[kc * GDIM + j];
        float4 wz = g_dWhh4[kc * GDIM + 128 + j];
        float4 wn = g_dWhh4[kc * GDIM + 256 + j];
#pragma unroll
        for (int nn = 0; nn < 4; ++nn) {
            float4 hv = hs4[(s + nn * 4) * 32 + kc];
            ar[nn] = fmaf(hv.x, wr.x, ar[nn]); ar[nn] = fmaf(hv.y, wr.y, ar[nn]);
            ar[nn] = fmaf(hv.z, wr.z, ar[nn]); ar[nn] = fmaf(hv.w, wr.w, ar[nn]);
            az[nn] = fmaf(hv.x, wz.x, az[nn]); az[nn] = fmaf(hv.y, wz.y, az[nn]);
            az[nn] = fmaf(hv.z, wz.z, az[nn]); az[nn] = fmaf(hv.w, wz.w, az[nn]);
            an[nn] = fmaf(hv.x, wn.x, an[nn]); an[nn] = fmaf(hv.y, wn.y, an[nn]);
            an[nn] = fmaf(hv.z, wn.z, an[nn]); an[nn] = fmaf(hv.w, wn.w, an[nn]);
        }
    }
    float bh_r = dbhh[j], bh_z = dbhh[j + 128], bh_n = dbhh[j + 256];
#pragma unroll
    for (int nn = 0; nn < 4; ++nn) {
        int b = s + nn * 4;
        float r = sigf(bi_r + bh_r + ar[nn]);
        float z = sigf(bi_z + bh_z + az[nn]);
        float n = tanhf_(bi_n + r * (an[nn] + bh_n));
        float h = hs[b * HDIM + j];
        float hv = n + z * (h - n);
        g_hall[((size_t)(b0 + b) * T_SEQ + 0) * HDIM + j] = hv;
        g_h1[(size_t)(b0 + b) * HDIM + j] = hv;
    }
}

// ---------------- decoder recurrence t=1..127: register-epilogue fp16 mma ----------------
__global__ __launch_bounds__(512, 1) void dec_tc_kernel(const float* __restrict__ dWhh,
                                                        const float* __restrict__ dbhh)
{
    extern __shared__ char smem[];
    uint32_t sb = smem_u32(smem);
    int tid = threadIdx.x, wid = tid >> 5, lane = tid & 31;
    int b0 = blockIdx.x * TB;

    // stage permuted fp16 W
    for (int idx = tid; idx < 512 * HDIM; idx += 512) {
        int p = idx >> 7, k = idx & 127;
        int w = p >> 5, q = p & 31, jr = 8 * w + (q & 7), gt = q >> 3;
        float v = (gt == 0) ? g_Wrz_rm[(size_t)jr * HDIM + k]
                : (gt == 1) ? g_Wrz_rm[(size_t)(128 + jr) * HDIM + k]
                : (gt == 2) ? dWhh[(size_t)(256 + jr) * HDIM + k]
                            : g_Wcn_rm[(size_t)jr * HDIM + k];
        *(__half*)(smem + D_W + p * WSTR + k * 2) = __float2half_rn(v);
    }
    __syncthreads();

    uint32_t whi[2][8][4];
    uint32_t baseA = sb + D_W + (wid * 32 + (lane & 15)) * WSTR + (lane >> 4) * 16;
#pragma unroll
    for (int m = 0; m < 2; ++m)
#pragma unroll
        for (int kc = 0; kc < 8; ++kc)
            LDSM4(whi[m][kc], baseA + m * 16 * WSTR + kc * 32);

    int gq = lane >> 2, tig = lane & 3;
    int j = 8 * wid + gq;
    float brz_r = g_brz[j], brz_z = g_brz[128 + j];
    float bcn = g_bcomb[256 + j], bh_n = dbhh[256 + j];
    int cv[4] = {2 * tig, 2 * tig + 1, 8 + 2 * tig, 9 + 2 * tig};
    uint32_t bB[2] = {sb + D_B0 + (lane & 7) * WSTR + (lane >> 3) * 16,
                      sb + D_B1 + (lane & 7) * WSTR + (lane >> 3) * 16};

    float hreg[4];
#pragma unroll
    for (int i = 0; i < 4; ++i) {
        int c = cv[i];
        float hv = g_h1[(size_t)(b0 + c) * HDIM + j];
        hreg[i] = hv;
        *(__half*)(smem + D_B0 + c * WSTR + j * 2) = __float2half_rn(hv);
    }
    __syncthreads();

    for (int tt = 0; tt < T_SEQ - 1; ++tt) {
        int cur = tt & 1;
        char* stbuf = smem + (cur ? D_B0 : D_B1) + j * 2;
        float d[2][2][4];
#pragma unroll
        for (int m = 0; m < 2; ++m)
#pragma unroll
            for (int n = 0; n < 2; ++n)
#pragma unroll
                for (int q = 0; q < 4; ++q) d[m][n][q] = 0.f;

#pragma unroll
        for (int kp = 0; kp < 4; ++kp) {
            uint32_t b0v[4], b1v[4];
            LDSM4(b0v, bB[cur] + kp * 64);
            LDSM4(b1v, bB[cur] + 8 * WSTR + kp * 64);
#pragma unroll
            for (int ch = 0; ch < 2; ++ch) {
                int kc = kp * 2 + ch;
#pragma unroll
                for (int m = 0; m < 2; ++m) {
                    MMA16816(d[m][0], whi[m][kc], b0v[2 * ch], b0v[2 * ch + 1]);
                    MMA16816(d[m][1], whi[m][kc], b1v[2 * ch], b1v[2 * ch + 1]);
                }
            }
        }

#pragma unroll
        for (int i = 0; i < 4; ++i) {
            int n = i >> 1, lo = i & 1, c = cv[i];
            float r = sigf(brz_r + d[0][n][lo]);
            float z = sigf(brz_z + d[0][n][2 + lo]);
            float nn = tanhf_(bcn + d[1][n][2 + lo] + r * (d[1][n][lo] + bh_n));
            float hv = nn + z * (hreg[i] - nn);
            hreg[i] = hv;
            g_hall[((size_t)(b0 + c) * T_SEQ + tt + 1) * HDIM + j] = hv;
            *(__half*)(stbuf + c * WSTR) = __float2half_rn(hv);
        }
        __syncthreads();
    }
}

// ---------------- out = g_hall @ lin_W^T + lin_b ----------------
__global__ void out_kernel(const float* __restrict__ linW, const float* __restrict__ linb,
                           float* __restrict__ out)
{
    __shared__ float hS[16 * HDIM];
    __shared__ float lS[HDIM * XDIM];
    int tx = threadIdx.x, ty = threadIdx.y;
    int tid = ty * XDIM + tx;
    int nthr = XDIM * 16;
    size_t r0 = (size_t)blockIdx.x * 16;

    for (int i = tid; i < 16 * HDIM; i += nthr) hS[i] = g_hall[r0 * HDIM + i];
    for (int i = tid; i < HDIM * XDIM; i += nthr) {
        int k = i / XDIM, p = i - k * XDIM;
        lS[i] = linW[p * HDIM + k];
    }
    __syncthreads();

    float acc = linb[tx];
    const float* hrow = hS + ty * HDIM;
#pragma unroll 8
    for (int k = 0; k < HDIM; ++k) acc = fmaf(hrow[k], lS[k * XDIM + tx], acc);
    out[(r0 + ty) * XDIM + tx] = acc;
}

// ---------------- launch ----------------
extern "C" void kernel_launch(void* const* d_in, const int* in_sizes, int n_in,
                              void* d_out, int out_size) {
    const float* x        = (const float*)d_in[0];
    const float* enc_Wih  = (const float*)d_in[1];
    const float* enc_Whh  = (const float*)d_in[2];
    const float* enc_bih  = (const float*)d_in[3];
    const float* enc_bhh  = (const float*)d_in[4];
    const float* dec_Wih  = (const float*)d_in[5];
    const float* dec_Whh  = (const float*)d_in[6];
    const float* dec_bih  = (const float*)d_in[7];
    const float* dec_bhh  = (const float*)d_in[8];
    const float* lin_W    = (const float*)d_in[9];
    const float* lin_b    = (const float*)d_in[10];
    float* out = (float*)d_out;

    cudaFuncSetAttribute(enc_tc_kernel, cudaFuncAttributeMaxDynamicSharedMemorySize, E_SZ);
    cudaFuncSetAttribute(dec_tc_kernel, cudaFuncAttributeMaxDynamicSharedMemorySize, D_SZ);

    prep_kernel<<<3, 128>>>(dec_Whh, dec_Wih, lin_W, lin_b, dec_bih, dec_bhh);
    enc_tc_kernel<<<NBATCH / TB, 512, E_SZ>>>(x, enc_Whh, enc_Wih, enc_bih, enc_bhh);
    dec0_kernel<<<NBATCH / TB, 512>>>(dec_bih, dec_bhh);
    dec_tc_kernel<<<NBATCH / TB, 512, D_SZ>>>(dec_Whh, dec_bhh);
    out_kernel<<<(NBATCH * T_SEQ) / 16, dim3(XDIM, 16)>>>(lin_W, lin_b, out);
}

// round 14
// speedup vs baseline: 1.8319x; 1.1507x over previous
#include <cuda_runtime.h>
#include <cuda_fp16.h>
#include <cstdint>

#define T_SEQ 128
#define NBATCH 2048
#define HDIM  128
#define GDIM  384
#define XDIM  38
#define TB    16

// ---------------- device scratch ----------------
__device__ float   g_hall[(size_t)NBATCH * T_SEQ * HDIM];  // [b][t][j]
__device__ float   g_h0[(size_t)NBATCH * HDIM];
__device__ float   g_h1[(size_t)NBATCH * HDIM];
__device__ float4  g_dWhh4[32 * GDIM];
__device__ float   g_Wrz_rm[256 * HDIM];
__device__ float   g_Wcn_rm[128 * HDIM];
__device__ float   g_bcomb[GDIM];
__device__ float   g_brz[256];

__device__ __forceinline__ float tanh_fast(float x) {
    float y;
    asm("tanh.approx.f32 %0, %1;" : "=f"(y) : "f"(x));
    return y;
}
__device__ __forceinline__ float sig_fast(float x) {
    return 0.5f + 0.5f * tanh_fast(0.5f * x);
}

__device__ __forceinline__ uint32_t smem_u32(const void* p) {
    uint32_t a;
    asm("{ .reg .u64 t; cvta.to.shared.u64 t, %1; cvt.u32.u64 %0, t; }" : "=r"(a) : "l"(p));
    return a;
}

#define LDSM4(r, a) \
    asm volatile("ldmatrix.sync.aligned.m8n8.x4.shared.b16 {%0,%1,%2,%3}, [%4];" \
        : "=r"((r)[0]), "=r"((r)[1]), "=r"((r)[2]), "=r"((r)[3]) : "r"(a))

#define MMA16816(d, a, b0, b1) \
    asm volatile("mma.sync.aligned.m16n8k16.row.col.f32.f16.f16.f32 " \
        "{%0,%1,%2,%3}, {%4,%5,%6,%7}, {%8,%9}, {%0,%1,%2,%3};" \
        : "+f"((d)[0]), "+f"((d)[1]), "+f"((d)[2]), "+f"((d)[3]) \
        : "r"((a)[0]), "r"((a)[1]), "r"((a)[2]), "r"((a)[3]), "r"(b0), "r"(b1))

#define WSTR 272

// ---- enc smem map ----
#define EW   0                 // 512*272 = 139264
#define EWX  139264            // 512*112 = 57344
#define EHB0 196608
#define EHB1 200960
#define EXB0 205312
#define EXB1 209664
#define E_SZ 214016
// ---- dec smem map ----
#define D_W  0
#define D_B0 139264
#define D_B1 143616
#define D_SZ 147968

// ---------------- weight prep: parallel over (g, kc) ----------------
__global__ __launch_bounds__(512) void prep_kernel(
    const float* __restrict__ dWhh, const float* __restrict__ dWih,
    const float* __restrict__ linW, const float* __restrict__ linb,
    const float* __restrict__ dbih, const float* __restrict__ dbhh)
{
    int idx = blockIdx.x * 512 + threadIdx.x;     // 0 .. GDIM*32-1
    if (idx >= GDIM * 32) return;
    int g = idx >> 5, kc = idx & 31;

    // transpose dec_Whh for dec0
    const float* dr = dWhh + (size_t)g * HDIM + kc * 4;
    float4 d4 = make_float4(dr[0], dr[1], dr[2], dr[3]);
    g_dWhh4[kc * GDIM + g] = d4;

    float wih[XDIM];
#pragma unroll
    for (int p = 0; p < XDIM; ++p) wih[p] = dWih[(size_t)g * XDIM + p];

    if (kc == 0) {
        float bc = dbih[g];
#pragma unroll
        for (int p = 0; p < XDIM; ++p) bc = fmaf(wih[p], linb[p], bc);
        g_bcomb[g] = bc;
        if (g < 256) g_brz[g] = bc + dbhh[g];
    }

    float a4[4] = {0.f, 0.f, 0.f, 0.f};
#pragma unroll
    for (int p = 0; p < XDIM; ++p) {
        float wv = wih[p];
        const float* lp = linW + (size_t)p * HDIM + kc * 4;
        a4[0] = fmaf(wv, lp[0], a4[0]);
        a4[1] = fmaf(wv, lp[1], a4[1]);
        a4[2] = fmaf(wv, lp[2], a4[2]);
        a4[3] = fmaf(wv, lp[3], a4[3]);
    }
    if (g < 256) {
        g_Wrz_rm[(size_t)g * HDIM + kc * 4 + 0] = a4[0] + d4.x;
        g_Wrz_rm[(size_t)g * HDIM + kc * 4 + 1] = a4[1] + d4.y;
        g_Wrz_rm[(size_t)g * HDIM + kc * 4 + 2] = a4[2] + d4.z;
        g_Wrz_rm[(size_t)g * HDIM + kc * 4 + 3] = a4[3] + d4.w;
    } else {
#pragma unroll
        for (int n = 0; n < 4; ++n) g_Wcn_rm[(size_t)(g - 256) * HDIM + kc * 4 + n] = a4[n];
    }
}

// ---------------- encoder: fused x-projection + recurrence ----------------
__global__ __launch_bounds__(512, 1) void enc_tc_kernel(
    const float* __restrict__ x,
    const float* __restrict__ eWhh, const float* __restrict__ eWih,
    const float* __restrict__ ebih, const float* __restrict__ ebhh)
{
    extern __shared__ char smem[];
    uint32_t sb = smem_u32(smem);
    int tid = threadIdx.x, wid = tid >> 5, lane = tid & 31;
    int b0 = blockIdx.x * TB;

    for (int idx = tid; idx < 512 * HDIM; idx += 512) {
        int p = idx >> 7, k = idx & 127;
        int w = p >> 5, q = p & 31, jr = 8 * w + (q & 7), gt = q >> 3;
        float v = (gt == 0) ? eWhh[(size_t)jr * HDIM + k]
                : (gt == 1) ? eWhh[(size_t)(128 + jr) * HDIM + k]
                : (gt == 2) ? eWhh[(size_t)(256 + jr) * HDIM + k] : 0.f;
        *(__half*)(smem + EW + p * WSTR + k * 2) = __float2half_rn(v);
    }
    for (int idx = tid; idx < 512 * 48; idx += 512) {
        int p = idx / 48, k = idx - p * 48;
        int w = p >> 5, q = p & 31, jr = 8 * w + (q & 7), gt = q >> 3;
        float v = 0.f;
        if (k < XDIM)
            v = (gt == 0) ? eWih[(size_t)jr * XDIM + k]
              : (gt == 1) ? eWih[(size_t)(128 + jr) * XDIM + k]
              : (gt == 3) ? eWih[(size_t)(256 + jr) * XDIM + k] : 0.f;
        *(__half*)(smem + EWX + p * 112 + k * 2) = __float2half_rn(v);
    }
    for (int i = tid; i < TB * HDIM; i += 512) {
        int c = i >> 7, j = i & 127;
        *(__half*)(smem + EHB0 + c * WSTR + j * 2) = __float2half_rn(0.f);
    }
    for (int i = tid; i < 2 * TB * 64; i += 512) {
        int buf = i >> 10, c = (i >> 6) & 15, k = i & 63;
        *(__half*)(smem + (buf ? EXB1 : EXB0) + c * WSTR + k * 2) = __float2half_rn(0.f);
    }
    for (int v = tid; v < TB * XDIM; v += 512) {
        int c = v / XDIM, k = v - c * XDIM;
        *(__half*)(smem + EXB0 + c * WSTR + k * 2) =
            __float2half_rn(x[((size_t)(b0 + c) * T_SEQ + 0) * XDIM + k]);
    }
    __syncthreads();

    uint32_t whi[2][8][4];
    uint32_t baseA  = sb + EW  + (wid * 32 + (lane & 15)) * WSTR + (lane >> 4) * 16;
    uint32_t baseAX = sb + EWX + (wid * 32 + (lane & 15)) * 112  + (lane >> 4) * 16;
#pragma unroll
    for (int m = 0; m < 2; ++m)
#pragma unroll
        for (int kc = 0; kc < 8; ++kc)
            LDSM4(whi[m][kc], baseA + m * 16 * WSTR + kc * 32);

    int gq = lane >> 2, tig = lane & 3;
    int j = 8 * wid + gq;
    float br = ebih[j] + ebhh[j];
    float bz = ebih[128 + j] + ebhh[128 + j];
    float bin = ebih[256 + j], bhn = ebhh[256 + j];
    int cv[4] = {2 * tig, 2 * tig + 1, 8 + 2 * tig, 9 + 2 * tig};
    float hreg[4] = {0.f, 0.f, 0.f, 0.f};
    uint32_t hB[2] = {sb + EHB0 + (lane & 7) * WSTR + (lane >> 3) * 16,
                      sb + EHB1 + (lane & 7) * WSTR + (lane >> 3) * 16};
    uint32_t xB[2] = {sb + EXB0 + (lane & 7) * WSTR + (lane >> 3) * 16,
                      sb + EXB1 + (lane & 7) * WSTR + (lane >> 3) * 16};
    int c0x = tid / XDIM, k0x = tid - c0x * XDIM;
    int v1 = tid + 512;
    int c1x = v1 / XDIM, k1x = v1 - c1x * XDIM;
    bool has1 = (v1 < TB * XDIM);

    for (int t = 0; t < T_SEQ; ++t) {
        int cur = t & 1;
        float xp0 = 0.f, xp1 = 0.f;
        if (t + 1 < T_SEQ) {
            xp0 = x[((size_t)(b0 + c0x) * T_SEQ + t + 1) * XDIM + k0x];
            if (has1) xp1 = x[((size_t)(b0 + c1x) * T_SEQ + t + 1) * XDIM + k1x];
        }

        float d[2][2][4];
#pragma unroll
        for (int m = 0; m < 2; ++m)
#pragma unroll
            for (int n = 0; n < 2; ++n)
#pragma unroll
                for (int q = 0; q < 4; ++q) d[m][n][q] = 0.f;

#pragma unroll
        for (int kp = 0; kp < 4; ++kp) {
            uint32_t b0v[4], b1v[4];
            LDSM4(b0v, hB[cur] + kp * 64);
            LDSM4(b1v, hB[cur] + 8 * WSTR + kp * 64);
#pragma unroll
            for (int ch = 0; ch < 2; ++ch) {
                int kc = kp * 2 + ch;
#pragma unroll
                for (int m = 0; m < 2; ++m) {
                    MMA16816(d[m][0], whi[m][kc], b0v[2 * ch], b0v[2 * ch + 1]);
                    MMA16816(d[m][1], whi[m][kc], b1v[2 * ch], b1v[2 * ch + 1]);
                }
            }
        }
#pragma unroll
        for (int kp = 0; kp < 2; ++kp) {
            uint32_t x0v[4], x1v[4];
            LDSM4(x0v, xB[cur] + kp * 64);
            LDSM4(x1v, xB[cur] + 8 * WSTR + kp * 64);
#pragma unroll
            for (int ch = 0; ch < 2; ++ch) {
                int kc = kp * 2 + ch;
                if (kc < 3) {
                    uint32_t a0[4], a1[4];
                    LDSM4(a0, baseAX + kc * 32);
                    LDSM4(a1, baseAX + 16 * 112 + kc * 32);
                    MMA16816(d[0][0], a0, x0v[2 * ch], x0v[2 * ch + 1]);
                    MMA16816(d[0][1], a0, x1v[2 * ch], x1v[2 * ch + 1]);
                    MMA16816(d[1][0], a1, x0v[2 * ch], x0v[2 * ch + 1]);
                    MMA16816(d[1][1], a1, x1v[2 * ch], x1v[2 * ch + 1]);
                }
            }
        }

        char* sth = smem + (cur ? EHB0 : EHB1) + j * 2;
#pragma unroll
        for (int i = 0; i < 4; ++i) {
            int nn = i >> 1, lo = i & 1, c = cv[i];
            float r = sig_fast(br + d[0][nn][lo]);
            float z = sig_fast(bz + d[0][nn][2 + lo]);
            float n = tanh_fast(bin + d[1][nn][2 + lo] + r * (d[1][nn][lo] + bhn));
            float hv = n + z * (hreg[i] - n);
            hreg[i] = hv;
            *(__half*)(sth + c * WSTR) = __float2half_rn(hv);
        }
        if (t + 1 < T_SEQ) {
            char* stx = smem + (cur ? EXB0 : EXB1);
            *(__half*)(stx + c0x * WSTR + k0x * 2) = __float2half_rn(xp0);
            if (has1) *(__half*)(stx + c1x * WSTR + k1x * 2) = __float2half_rn(xp1);
        }
        __syncthreads();
    }

#pragma unroll
    for (int i = 0; i < 4; ++i)
        g_h0[(size_t)(b0 + cv[i]) * HDIM + j] = hreg[i];
}

// ---------------- decoder t=0 (plain FFMA) ----------------
__global__ __launch_bounds__(512, 1) void dec0_kernel(const float* __restrict__ dbih,
                                                      const float* __restrict__ dbhh)
{
    __shared__ float4 hs4[TB * 32];
    float* hs = (float*)hs4;
    int tid = threadIdx.x;
    int j = tid & 127, s = tid >> 7;
    int b0 = blockIdx.x * TB;

    for (int i = tid; i < TB * HDIM; i += 512) hs[i] = g_h0[(size_t)b0 * HDIM + i];
    float bi_r = dbih[j], bi_z = dbih[j + 128], bi_n = dbih[j + 256];
    __syncthreads();

    float ar[4] = {0, 0, 0, 0}, az[4] = {0, 0, 0, 0}, an[4] = {0, 0, 0, 0};
#pragma unroll 4
    for (int kc = 0; kc < 32; ++kc) {
        float4 wr = g_dWhh4[kc * GDIM + j];
        float4 wz = g_dWhh4[kc * GDIM + 128 + j];
        float4 wn = g_dWhh4[kc * GDIM + 256 + j];
#pragma unroll
        for (int nn = 0; nn < 4; ++nn) {
            float4 hv = hs4[(s + nn * 4) * 32 + kc];
            ar[nn] = fmaf(hv.x, wr.x, ar[nn]); ar[nn] = fmaf(hv.y, wr.y, ar[nn]);
            ar[nn] = fmaf(hv.z, wr.z, ar[nn]); ar[nn] = fmaf(hv.w, wr.w, ar[nn]);
            az[nn] = fmaf(hv.x, wz.x, az[nn]); az[nn] = fmaf(hv.y, wz.y, az[nn]);
            az[nn] = fmaf(hv.z, wz.z, az[nn]); az[nn] = fmaf(hv.w, wz.w, az[nn]);
            an[nn] = fmaf(hv.x, wn.x, an[nn]); an[nn] = fmaf(hv.y, wn.y, an[nn]);
            an[nn] = fmaf(hv.z, wn.z, an[nn]); an[nn] = fmaf(hv.w, wn.w, an[nn]);
        }
    }
    float bh_r = dbhh[j], bh_z = dbhh[j + 128], bh_n = dbhh[j + 256];
#pragma unroll
    for (int nn = 0; nn < 4; ++nn) {
        int b = s + nn * 4;
        float r = sig_fast(bi_r + bh_r + ar[nn]);
        float z = sig_fast(bi_z + bh_z + az[nn]);
        float n = tanh_fast(bi_n + r * (an[nn] + bh_n));
        float h = hs[b * HDIM + j];
        float hv = n + z * (h - n);
        g_hall[((size_t)(b0 + b) * T_SEQ + 0) * HDIM + j] = hv;
        g_h1[(size_t)(b0 + b) * HDIM + j] = hv;
    }
}

// ---------------- decoder recurrence t=1..127 ----------------
__global__ __launch_bounds__(512, 1) void dec_tc_kernel(const float* __restrict__ dWhh,
                                                        const float* __restrict__ dbhh)
{
    extern __shared__ char smem[];
    uint32_t sb = smem_u32(smem);
    int tid = threadIdx.x, wid = tid >> 5, lane = tid & 31;
    int b0 = blockIdx.x * TB;

    for (int idx = tid; idx < 512 * HDIM; idx += 512) {
        int p = idx >> 7, k = idx & 127;
        int w = p >> 5, q = p & 31, jr = 8 * w + (q & 7), gt = q >> 3;
        float v = (gt == 0) ? g_Wrz_rm[(size_t)jr * HDIM + k]
                : (gt == 1) ? g_Wrz_rm[(size_t)(128 + jr) * HDIM + k]
                : (gt == 2) ? dWhh[(size_t)(256 + jr) * HDIM + k]
                            : g_Wcn_rm[(size_t)jr * HDIM + k];
        *(__half*)(smem + D_W + p * WSTR + k * 2) = __float2half_rn(v);
    }
    __syncthreads();

    uint32_t whi[2][8][4];
    uint32_t baseA = sb + D_W + (wid * 32 + (lane & 15)) * WSTR + (lane >> 4) * 16;
#pragma unroll
    for (int m = 0; m < 2; ++m)
#pragma unroll
        for (int kc = 0; kc < 8; ++kc)
            LDSM4(whi[m][kc], baseA + m * 16 * WSTR + kc * 32);

    int gq = lane >> 2, tig = lane & 3;
    int j = 8 * wid + gq;
    float brz_r = g_brz[j], brz_z = g_brz[128 + j];
    float bcn = g_bcomb[256 + j], bh_n = dbhh[256 + j];
    int cv[4] = {2 * tig, 2 * tig + 1, 8 + 2 * tig, 9 + 2 * tig};
    uint32_t bB[2] = {sb + D_B0 + (lane & 7) * WSTR + (lane >> 3) * 16,
                      sb + D_B1 + (lane & 7) * WSTR + (lane >> 3) * 16};

    float hreg[4];
#pragma unroll
    for (int i = 0; i < 4; ++i) {
        int c = cv[i];
        float hv = g_h1[(size_t)(b0 + c) * HDIM + j];
        hreg[i] = hv;
        *(__half*)(smem + D_B0 + c * WSTR + j * 2) = __float2half_rn(hv);
    }
    __syncthreads();

    for (int tt = 0; tt < T_SEQ - 1; ++tt) {
        int cur = tt & 1;
        char* stbuf = smem + (cur ? D_B0 : D_B1) + j * 2;
        float d[2][2][4];
#pragma unroll
        for (int m = 0; m < 2; ++m)
#pragma unroll
            for (int n = 0; n < 2; ++n)
#pragma unroll
                for (int q = 0; q < 4; ++q) d[m][n][q] = 0.f;

#pragma unroll
        for (int kp = 0; kp < 4; ++kp) {
            uint32_t b0v[4], b1v[4];
            LDSM4(b0v, bB[cur] + kp * 64);
            LDSM4(b1v, bB[cur] + 8 * WSTR + kp * 64);
#pragma unroll
            for (int ch = 0; ch < 2; ++ch) {
                int kc = kp * 2 + ch;
#pragma unroll
                for (int m = 0; m < 2; ++m) {
                    MMA16816(d[m][0], whi[m][kc], b0v[2 * ch], b0v[2 * ch + 1]);
                    MMA16816(d[m][1], whi[m][kc], b1v[2 * ch], b1v[2 * ch + 1]);
                }
            }
        }

#pragma unroll
        for (int i = 0; i < 4; ++i) {
            int n = i >> 1, lo = i & 1, c = cv[i];
            float r = sig_fast(brz_r + d[0][n][lo]);
            float z = sig_fast(brz_z + d[0][n][2 + lo]);
            float nn = tanh_fast(bcn + d[1][n][2 + lo] + r * (d[1][n][lo] + bh_n));
            float hv = nn + z * (hreg[i] - nn);
            hreg[i] = hv;
            g_hall[((size_t)(b0 + c) * T_SEQ + tt + 1) * HDIM + j] = hv;
            *(__half*)(stbuf + c * WSTR) = __float2half_rn(hv);
        }
        __syncthreads();
    }
}

// ---------------- out = g_hall @ lin_W^T + lin_b  (64 rows/block) ----------------
__global__ void out_kernel(const float* __restrict__ linW, const float* __restrict__ linb,
                           float* __restrict__ out)
{
    __shared__ float hS[64 * HDIM];      // 32 KB
    __shared__ float lS[HDIM * XDIM];    // 19.4 KB
    int tx = threadIdx.x, ty = threadIdx.y;
    int tid = ty * XDIM + tx;
    int nthr = XDIM * 16;
    size_t r0 = (size_t)blockIdx.x * 64;

    for (int i = tid; i < 64 * HDIM; i += nthr) hS[i] = g_hall[r0 * HDIM + i];
    for (int i = tid; i < HDIM * XDIM; i += nthr) {
        int k = i / XDIM, p = i - k * XDIM;
        lS[i] = linW[p * HDIM + k];
    }
    __syncthreads();

    float bias = linb[tx];
#pragma unroll
    for (int rb = 0; rb < 4; ++rb) {
        int row = rb * 16 + ty;
        float acc = bias;
        const float* hrow = hS + row * HDIM;
#pragma unroll 8
        for (int k = 0; k < HDIM; ++k) acc = fmaf(hrow[k], lS[k * XDIM + tx], acc);
        out[(r0 + row) * XDIM + tx] = acc;
    }
}

// ---------------- launch ----------------
extern "C" void kernel_launch(void* const* d_in, const int* in_sizes, int n_in,
                              void* d_out, int out_size) {
    const float* x        = (const float*)d_in[0];
    const float* enc_Wih  = (const float*)d_in[1];
    const float* enc_Whh  = (const float*)d_in[2];
    const float* enc_bih  = (const float*)d_in[3];
    const float* enc_bhh  = (const float*)d_in[4];
    const float* dec_Wih  = (const float*)d_in[5];
    const float* dec_Whh  = (const float*)d_in[6];
    const float* dec_bih  = (const float*)d_in[7];
    const float* dec_bhh  = (const float*)d_in[8];
    const float* lin_W    = (const float*)d_in[9];
    const float* lin_b    = (const float*)d_in[10];
    float* out = (float*)d_out;

    cudaFuncSetAttribute(enc_tc_kernel, cudaFuncAttributeMaxDynamicSharedMemorySize, E_SZ);
    cudaFuncSetAttribute(dec_tc_kernel, cudaFuncAttributeMaxDynamicSharedMemorySize, D_SZ);

    prep_kernel<<<24, 512>>>(dec_Whh, dec_Wih, lin_W, lin_b, dec_bih, dec_bhh);
    enc_tc_kernel<<<NBATCH / TB, 512, E_SZ>>>(x, enc_Whh, enc_Wih, enc_bih, enc_bhh);
    dec0_kernel<<<NBATCH / TB, 512>>>(dec_bih, dec_bhh);
    dec_tc_kernel<<<NBATCH / TB, 512, D_SZ>>>(dec_Whh, dec_bhh);
    out_kernel<<<(NBATCH * T_SEQ) / 64, dim3(XDIM, 16)>>>(lin_W, lin_b, out);
}

// round 15
// speedup vs baseline: 3.6909x; 2.0148x over previous
#include <cuda_runtime.h>
#include <cuda_fp16.h>
#include <cstdint>

#define T_SEQ 128
#define NBATCH 2048
#define HDIM  128
#define GDIM  384
#define XDIM  38
#define TB    16

// ---------------- device scratch ----------------
__device__ __half  g_hall_h[(size_t)NBATCH * T_SEQ * HDIM];  // fp16 hiddens [b][t][j]
__device__ float   g_h0[(size_t)NBATCH * HDIM];
__device__ float   g_h1[(size_t)NBATCH * HDIM];
__device__ float4  g_dWhh4[32 * GDIM];
__device__ float   g_Wrz_rm[256 * HDIM];
__device__ float   g_Wcn_rm[128 * HDIM];
__device__ float   g_bcomb[GDIM];
__device__ float   g_brz[256];

__device__ __forceinline__ float tanh_fast(float x) {
    float y;
    asm("tanh.approx.f32 %0, %1;" : "=f"(y) : "f"(x));
    return y;
}
__device__ __forceinline__ float sig_fast(float x) {
    return 0.5f + 0.5f * tanh_fast(0.5f * x);
}

__device__ __forceinline__ uint32_t smem_u32(const void* p) {
    uint32_t a;
    asm("{ .reg .u64 t; cvta.to.shared.u64 t, %1; cvt.u32.u64 %0, t; }" : "=r"(a) : "l"(p));
    return a;
}

#define LDSM4(r, a) \
    asm volatile("ldmatrix.sync.aligned.m8n8.x4.shared.b16 {%0,%1,%2,%3}, [%4];" \
        : "=r"((r)[0]), "=r"((r)[1]), "=r"((r)[2]), "=r"((r)[3]) : "r"(a))

#define MMA16816(d, a, b0, b1) \
    asm volatile("mma.sync.aligned.m16n8k16.row.col.f32.f16.f16.f32 " \
        "{%0,%1,%2,%3}, {%4,%5,%6,%7}, {%8,%9}, {%0,%1,%2,%3};" \
        : "+f"((d)[0]), "+f"((d)[1]), "+f"((d)[2]), "+f"((d)[3]) \
        : "r"((a)[0]), "r"((a)[1]), "r"((a)[2]), "r"((a)[3]), "r"(b0), "r"(b1))

#define WSTR 272

// ---- enc smem map ----
#define EW   0                 // 512*272 = 139264
#define EWX  139264            // 512*112 = 57344
#define EHB0 196608
#define EHB1 200960
#define EXB0 205312
#define EXB1 209664
#define E_SZ 214016
// ---- dec smem map ----
#define D_W  0
#define D_B0 139264
#define D_B1 143616
#define D_SZ 147968

// ---------------- weight prep: parallel over (g, kc) ----------------
__global__ __launch_bounds__(512) void prep_kernel(
    const float* __restrict__ dWhh, const float* __restrict__ dWih,
    const float* __restrict__ linW, const float* __restrict__ linb,
    const float* __restrict__ dbih, const float* __restrict__ dbhh)
{
    int idx = blockIdx.x * 512 + threadIdx.x;
    if (idx >= GDIM * 32) return;
    int g = idx >> 5, kc = idx & 31;

    const float* dr = dWhh + (size_t)g * HDIM + kc * 4;
    float4 d4 = make_float4(dr[0], dr[1], dr[2], dr[3]);
    g_dWhh4[kc * GDIM + g] = d4;

    float wih[XDIM];
#pragma unroll
    for (int p = 0; p < XDIM; ++p) wih[p] = dWih[(size_t)g * XDIM + p];

    if (kc == 0) {
        float bc = dbih[g];
#pragma unroll
        for (int p = 0; p < XDIM; ++p) bc = fmaf(wih[p], linb[p], bc);
        g_bcomb[g] = bc;
        if (g < 256) g_brz[g] = bc + dbhh[g];
    }

    float a4[4] = {0.f, 0.f, 0.f, 0.f};
#pragma unroll
    for (int p = 0; p < XDIM; ++p) {
        float wv = wih[p];
        const float* lp = linW + (size_t)p * HDIM + kc * 4;
        a4[0] = fmaf(wv, lp[0], a4[0]);
        a4[1] = fmaf(wv, lp[1], a4[1]);
        a4[2] = fmaf(wv, lp[2], a4[2]);
        a4[3] = fmaf(wv, lp[3], a4[3]);
    }
    if (g < 256) {
        g_Wrz_rm[(size_t)g * HDIM + kc * 4 + 0] = a4[0] + d4.x;
        g_Wrz_rm[(size_t)g * HDIM + kc * 4 + 1] = a4[1] + d4.y;
        g_Wrz_rm[(size_t)g * HDIM + kc * 4 + 2] = a4[2] + d4.z;
        g_Wrz_rm[(size_t)g * HDIM + kc * 4 + 3] = a4[3] + d4.w;
    } else {
#pragma unroll
        for (int n = 0; n < 4; ++n) g_Wcn_rm[(size_t)(g - 256) * HDIM + kc * 4 + n] = a4[n];
    }
}

// ---------------- encoder: fused x-projection + recurrence ----------------
__global__ __launch_bounds__(512, 1) void enc_tc_kernel(
    const float* __restrict__ x,
    const float* __restrict__ eWhh, const float* __restrict__ eWih,
    const float* __restrict__ ebih, const float* __restrict__ ebhh)
{
    extern __shared__ char smem[];
    uint32_t sb = smem_u32(smem);
    int tid = threadIdx.x, wid = tid >> 5, lane = tid & 31;
    int b0 = blockIdx.x * TB;

    for (int idx = tid; idx < 512 * HDIM; idx += 512) {
        int p = idx >> 7, k = idx & 127;
        int w = p >> 5, q = p & 31, jr = 8 * w + (q & 7), gt = q >> 3;
        float v = (gt == 0) ? eWhh[(size_t)jr * HDIM + k]
                : (gt == 1) ? eWhh[(size_t)(128 + jr) * HDIM + k]
                : (gt == 2) ? eWhh[(size_t)(256 + jr) * HDIM + k] : 0.f;
        *(__half*)(smem + EW + p * WSTR + k * 2) = __float2half_rn(v);
    }
    for (int idx = tid; idx < 512 * 48; idx += 512) {
        int p = idx / 48, k = idx - p * 48;
        int w = p >> 5, q = p & 31, jr = 8 * w + (q & 7), gt = q >> 3;
        float v = 0.f;
        if (k < XDIM)
            v = (gt == 0) ? eWih[(size_t)jr * XDIM + k]
              : (gt == 1) ? eWih[(size_t)(128 + jr) * XDIM + k]
              : (gt == 3) ? eWih[(size_t)(256 + jr) * XDIM + k] : 0.f;
        *(__half*)(smem + EWX + p * 112 + k * 2) = __float2half_rn(v);
    }
    for (int i = tid; i < TB * HDIM; i += 512) {
        int c = i >> 7, j = i & 127;
        *(__half*)(smem + EHB0 + c * WSTR + j * 2) = __float2half_rn(0.f);
    }
    for (int i = tid; i < 2 * TB * 64; i += 512) {
        int buf = i >> 10, c = (i >> 6) & 15, k = i & 63;
        *(__half*)(smem + (buf ? EXB1 : EXB0) + c * WSTR + k * 2) = __float2half_rn(0.f);
    }
    for (int v = tid; v < TB * XDIM; v += 512) {
        int c = v / XDIM, k = v - c * XDIM;
        *(__half*)(smem + EXB0 + c * WSTR + k * 2) =
            __float2half_rn(x[((size_t)(b0 + c) * T_SEQ + 0) * XDIM + k]);
    }
    __syncthreads();

    uint32_t whi[2][8][4];
    uint32_t baseA  = sb + EW  + (wid * 32 + (lane & 15)) * WSTR + (lane >> 4) * 16;
    uint32_t baseAX = sb + EWX + (wid * 32 + (lane & 15)) * 112  + (lane >> 4) * 16;
#pragma unroll
    for (int m = 0; m < 2; ++m)
#pragma unroll
        for (int kc = 0; kc < 8; ++kc)
            LDSM4(whi[m][kc], baseA + m * 16 * WSTR + kc * 32);

    int gq = lane >> 2, tig = lane & 3;
    int j = 8 * wid + gq;
    float br = ebih[j] + ebhh[j];
    float bz = ebih[128 + j] + ebhh[128 + j];
    float bin = ebih[256 + j], bhn = ebhh[256 + j];
    int cv[4] = {2 * tig, 2 * tig + 1, 8 + 2 * tig, 9 + 2 * tig};
    float hreg[4] = {0.f, 0.f, 0.f, 0.f};
    uint32_t hB[2] = {sb + EHB0 + (lane & 7) * WSTR + (lane >> 3) * 16,
                      sb + EHB1 + (lane & 7) * WSTR + (lane >> 3) * 16};
    uint32_t xB[2] = {sb + EXB0 + (lane & 7) * WSTR + (lane >> 3) * 16,
                      sb + EXB1 + (lane & 7) * WSTR + (lane >> 3) * 16};
    int c0x = tid / XDIM, k0x = tid - c0x * XDIM;
    int v1 = tid + 512;
    int c1x = v1 / XDIM, k1x = v1 - c1x * XDIM;
    bool has1 = (v1 < TB * XDIM);

    for (int t = 0; t < T_SEQ; ++t) {
        int cur = t & 1;
        float xp0 = 0.f, xp1 = 0.f;
        if (t + 1 < T_SEQ) {
            xp0 = x[((size_t)(b0 + c0x) * T_SEQ + t + 1) * XDIM + k0x];
            if (has1) xp1 = x[((size_t)(b0 + c1x) * T_SEQ + t + 1) * XDIM + k1x];
        }

        float d[2][2][4];
#pragma unroll
        for (int m = 0; m < 2; ++m)
#pragma unroll
            for (int n = 0; n < 2; ++n)
#pragma unroll
                for (int q = 0; q < 4; ++q) d[m][n][q] = 0.f;

#pragma unroll
        for (int kp = 0; kp < 4; ++kp) {
            uint32_t b0v[4], b1v[4];
            LDSM4(b0v, hB[cur] + kp * 64);
            LDSM4(b1v, hB[cur] + 8 * WSTR + kp * 64);
#pragma unroll
            for (int ch = 0; ch < 2; ++ch) {
                int kc = kp * 2 + ch;
#pragma unroll
                for (int m = 0; m < 2; ++m) {
                    MMA16816(d[m][0], whi[m][kc], b0v[2 * ch], b0v[2 * ch + 1]);
                    MMA16816(d[m][1], whi[m][kc], b1v[2 * ch], b1v[2 * ch + 1]);
                }
            }
        }
#pragma unroll
        for (int kp = 0; kp < 2; ++kp) {
            uint32_t x0v[4], x1v[4];
            LDSM4(x0v, xB[cur] + kp * 64);
            LDSM4(x1v, xB[cur] + 8 * WSTR + kp * 64);
#pragma unroll
            for (int ch = 0; ch < 2; ++ch) {
                int kc = kp * 2 + ch;
                if (kc < 3) {
                    uint32_t a0[4], a1[4];
                    LDSM4(a0, baseAX + kc * 32);
                    LDSM4(a1, baseAX + 16 * 112 + kc * 32);
                    MMA16816(d[0][0], a0, x0v[2 * ch], x0v[2 * ch + 1]);
                    MMA16816(d[0][1], a0, x1v[2 * ch], x1v[2 * ch + 1]);
                    MMA16816(d[1][0], a1, x0v[2 * ch], x0v[2 * ch + 1]);
                    MMA16816(d[1][1], a1, x1v[2 * ch], x1v[2 * ch + 1]);
                }
            }
        }

        char* sth = smem + (cur ? EHB0 : EHB1) + j * 2;
#pragma unroll
        for (int i = 0; i < 4; ++i) {
            int nn = i >> 1, lo = i & 1, c = cv[i];
            float r = sig_fast(br + d[0][nn][lo]);
            float z = sig_fast(bz + d[0][nn][2 + lo]);
            float n = tanh_fast(bin + d[1][nn][2 + lo] + r * (d[1][nn][lo] + bhn));
            float hv = n + z * (hreg[i] - n);
            hreg[i] = hv;
            *(__half*)(sth + c * WSTR) = __float2half_rn(hv);
        }
        if (t + 1 < T_SEQ) {
            char* stx = smem + (cur ? EXB0 : EXB1);
            *(__half*)(stx + c0x * WSTR + k0x * 2) = __float2half_rn(xp0);
            if (has1) *(__half*)(stx + c1x * WSTR + k1x * 2) = __float2half_rn(xp1);
        }
        __syncthreads();
    }

#pragma unroll
    for (int i = 0; i < 4; ++i)
        g_h0[(size_t)(b0 + cv[i]) * HDIM + j] = hreg[i];
}

// ---------------- decoder t=0 (plain FFMA) ----------------
__global__ __launch_bounds__(512, 1) void dec0_kernel(const float* __restrict__ dbih,
                                                      const float* __restrict__ dbhh)
{
    __shared__ float4 hs4[TB * 32];
    float* hs = (float*)hs4;
    int tid = threadIdx.x;
    int j = tid & 127, s = tid >> 7;
    int b0 = blockIdx.x * TB;

    for (int i = tid; i < TB * HDIM; i += 512) hs[i] = g_h0[(size_t)b0 * HDIM + i];
    float bi_r = dbih[j], bi_z = dbih[j + 128], bi_n = dbih[j + 256];
    __syncthreads();

    float ar[4] = {0, 0, 0, 0}, az[4] = {0, 0, 0, 0}, an[4] = {0, 0, 0, 0};
#pragma unroll 4
    for (int kc = 0; kc < 32; ++kc) {
        float4 wr = g_dWhh4[kc * GDIM + j];
        float4 wz = g_dWhh4[kc * GDIM + 128 + j];
        float4 wn = g_dWhh4[kc * GDIM + 256 + j];
#pragma unroll
        for (int nn = 0; nn < 4; ++nn) {
            float4 hv = hs4[(s + nn * 4) * 32 + kc];
            ar[nn] = fmaf(hv.x, wr.x, ar[nn]); ar[nn] = fmaf(hv.y, wr.y, ar[nn]);
            ar[nn] = fmaf(hv.z, wr.z, ar[nn]); ar[nn] = fmaf(hv.w, wr.w, ar[nn]);
            az[nn] = fmaf(hv.x, wz.x, az[nn]); az[nn] = fmaf(hv.y, wz.y, az[nn]);
            az[nn] = fmaf(hv.z, wz.z, az[nn]); az[nn] = fmaf(hv.w, wz.w, az[nn]);
            an[nn] = fmaf(hv.x, wn.x, an[nn]); an[nn] = fmaf(hv.y, wn.y, an[nn]);
            an[nn] = fmaf(hv.z, wn.z, an[nn]); an[nn] = fmaf(hv.w, wn.w, an[nn]);
        }
    }
    float bh_r = dbhh[j], bh_z = dbhh[j + 128], bh_n = dbhh[j + 256];
#pragma unroll
    for (int nn = 0; nn < 4; ++nn) {
        int b = s + nn * 4;
        float r = sig_fast(bi_r + bh_r + ar[nn]);
        float z = sig_fast(bi_z + bh_z + az[nn]);
        float n = tanh_fast(bi_n + r * (an[nn] + bh_n));
        float h = hs[b * HDIM + j];
        float hv = n + z * (h - n);
        g_hall_h[((size_t)(b0 + b) * T_SEQ + 0) * HDIM + j] = __float2half_rn(hv);
        g_h1[(size_t)(b0 + b) * HDIM + j] = hv;
    }
}

// ---------------- decoder recurrence t=1..127 ----------------
__global__ __launch_bounds__(512, 1) void dec_tc_kernel(const float* __restrict__ dWhh,
                                                        const float* __restrict__ dbhh)
{
    extern __shared__ char smem[];
    uint32_t sb = smem_u32(smem);
    int tid = threadIdx.x, wid = tid >> 5, lane = tid & 31;
    int b0 = blockIdx.x * TB;

    for (int idx = tid; idx < 512 * HDIM; idx += 512) {
        int p = idx >> 7, k = idx & 127;
        int w = p >> 5, q = p & 31, jr = 8 * w + (q & 7), gt = q >> 3;
        float v = (gt == 0) ? g_Wrz_rm[(size_t)jr * HDIM + k]
                : (gt == 1) ? g_Wrz_rm[(size_t)(128 + jr) * HDIM + k]
                : (gt == 2) ? dWhh[(size_t)(256 + jr) * HDIM + k]
                            : g_Wcn_rm[(size_t)jr * HDIM + k];
        *(__half*)(smem + D_W + p * WSTR + k * 2) = __float2half_rn(v);
    }
    __syncthreads();

    uint32_t whi[2][8][4];
    uint32_t baseA = sb + D_W + (wid * 32 + (lane & 15)) * WSTR + (lane >> 4) * 16;
#pragma unroll
    for (int m = 0; m < 2; ++m)
#pragma unroll
        for (int kc = 0; kc < 8; ++kc)
            LDSM4(whi[m][kc], baseA + m * 16 * WSTR + kc * 32);

    int gq = lane >> 2, tig = lane & 3;
    int j = 8 * wid + gq;
    float brz_r = g_brz[j], brz_z = g_brz[128 + j];
    float bcn = g_bcomb[256 + j], bh_n = dbhh[256 + j];
    int cv[4] = {2 * tig, 2 * tig + 1, 8 + 2 * tig, 9 + 2 * tig};
    uint32_t bB[2] = {sb + D_B0 + (lane & 7) * WSTR + (lane >> 3) * 16,
                      sb + D_B1 + (lane & 7) * WSTR + (lane >> 3) * 16};

    float hreg[4];
#pragma unroll
    for (int i = 0; i < 4; ++i) {
        int c = cv[i];
        float hv = g_h1[(size_t)(b0 + c) * HDIM + j];
        hreg[i] = hv;
        *(__half*)(smem + D_B0 + c * WSTR + j * 2) = __float2half_rn(hv);
    }
    __syncthreads();

    for (int tt = 0; tt < T_SEQ - 1; ++tt) {
        int cur = tt & 1;

        // coalesced hall write: warp wid copies batch-row wid of the CURRENT
        // buffer (= h at time tt) to g_hall_h[.., tt, ..]; overlaps the mma.
        {
            const char* cbuf = smem + (cur ? D_B1 : D_B0);
            uint2 hv2 = *(const uint2*)(cbuf + wid * WSTR + lane * 8);
            *(uint2*)&g_hall_h[((size_t)(b0 + wid) * T_SEQ + tt) * HDIM + lane * 4] = hv2;
        }

        char* stbuf = smem + (cur ? D_B0 : D_B1) + j * 2;
        float d[2][2][4];
#pragma unroll
        for (int m = 0; m < 2; ++m)
#pragma unroll
            for (int n = 0; n < 2; ++n)
#pragma unroll
                for (int q = 0; q < 4; ++q) d[m][n][q] = 0.f;

#pragma unroll
        for (int kp = 0; kp < 4; ++kp) {
            uint32_t b0v[4], b1v[4];
            LDSM4(b0v, bB[cur] + kp * 64);
            LDSM4(b1v, bB[cur] + 8 * WSTR + kp * 64);
#pragma unroll
            for (int ch = 0; ch < 2; ++ch) {
                int kc = kp * 2 + ch;
#pragma unroll
                for (int m = 0; m < 2; ++m) {
                    MMA16816(d[m][0], whi[m][kc], b0v[2 * ch], b0v[2 * ch + 1]);
                    MMA16816(d[m][1], whi[m][kc], b1v[2 * ch], b1v[2 * ch + 1]);
                }
            }
        }

#pragma unroll
        for (int i = 0; i < 4; ++i) {
            int n = i >> 1, lo = i & 1, c = cv[i];
            float r = sig_fast(brz_r + d[0][n][lo]);
            float z = sig_fast(brz_z + d[0][n][2 + lo]);
            float nn = tanh_fast(bcn + d[1][n][2 + lo] + r * (d[1][n][lo] + bh_n));
            float hv = nn + z * (hreg[i] - nn);
            hreg[i] = hv;
            *(__half*)(stbuf + c * WSTR) = __float2half_rn(hv);
        }
        __syncthreads();
    }

    // tail: buffer[1] holds h(127)
    {
        const char* cbuf = smem + D_B1;
        uint2 hv2 = *(const uint2*)(cbuf + wid * WSTR + lane * 8);
        *(uint2*)&g_hall_h[((size_t)(b0 + wid) * T_SEQ + 127) * HDIM + lane * 4] = hv2;
    }
}

// ---------------- out = hall_h @ lin_W^T + lin_b  (tensor-core) ----------------
// block: 256 thr (8 warps), 128 rows; warp w owns rows 16w..16w+15.
__global__ __launch_bounds__(256) void out_mma_kernel(
    const float* __restrict__ linW, const float* __restrict__ linb,
    float* __restrict__ out)
{
    __shared__ char sm[128 * WSTR + 40 * WSTR];
    char* hallS = sm;
    char* linS  = sm + 128 * WSTR;
    uint32_t sbh = smem_u32(hallS);
    uint32_t sbl = smem_u32(linS);
    int tid = threadIdx.x, wid = tid >> 5, lane = tid & 31;
    size_t r0 = (size_t)blockIdx.x * 128;

    // stage 128 hall rows (fp16, 256B each)
    const uint4* src = (const uint4*)(g_hall_h + r0 * HDIM);
    for (int i = tid; i < 128 * 16; i += 256) {
        int r = i >> 4, q = i & 15;
        *(uint4*)(hallS + r * WSTR + q * 16) = src[r * 16 + q];
    }
    // stage lin (40 rows padded, fp16)
    for (int i = tid; i < 40 * HDIM; i += 256) {
        int f = i >> 7, k = i & 127;
        float v = (f < XDIM) ? linW[(size_t)f * HDIM + k] : 0.f;
        *(__half*)(linS + f * WSTR + k * 2) = __float2half_rn(v);
    }
    __syncthreads();

    uint32_t a[8][4];
    uint32_t baseA = sbh + (wid * 16 + (lane & 15)) * WSTR + (lane >> 4) * 16;
#pragma unroll
    for (int kc = 0; kc < 8; ++kc) LDSM4(a[kc], baseA + kc * 32);

    uint32_t baseB = sbl + (lane & 7) * WSTR + (lane >> 3) * 16;
    float d[5][4];
#pragma unroll
    for (int nt = 0; nt < 5; ++nt)
#pragma unroll
        for (int q = 0; q < 4; ++q) d[nt][q] = 0.f;

#pragma unroll
    for (int nt = 0; nt < 5; ++nt)
#pragma unroll
        for (int kp = 0; kp < 4; ++kp) {
            uint32_t bv[4];
            LDSM4(bv, baseB + nt * 8 * WSTR + kp * 64);
#pragma unroll
            for (int ch = 0; ch < 2; ++ch)
                MMA16816(d[nt], a[kp * 2 + ch], bv[2 * ch], bv[2 * ch + 1]);
        }

    int gq = lane >> 2, tig = lane & 3;
#pragma unroll
    for (int nt = 0; nt < 5; ++nt)
#pragma unroll
        for (int q = 0; q < 4; ++q) {
            int row = wid * 16 + gq + ((q >> 1) ? 8 : 0);
            int col = nt * 8 + 2 * tig + (q & 1);
            if (col < XDIM)
                out[(r0 + row) * XDIM + col] = d[nt][q] + linb[col];
        }
}

// ---------------- launch ----------------
extern "C" void kernel_launch(void* const* d_in, const int* in_sizes, int n_in,
                              void* d_out, int out_size) {
    const float* x        = (const float*)d_in[0];
    const float* enc_Wih  = (const float*)d_in[1];
    const float* enc_Whh  = (const float*)d_in[2];
    const float* enc_bih  = (const float*)d_in[3];
    const float* enc_bhh  = (const float*)d_in[4];
    const float* dec_Wih  = (const float*)d_in[5];
    const float* dec_Whh  = (const float*)d_in[6];
    const float* dec_bih  = (const float*)d_in[7];
    const float* dec_bhh  = (const float*)d_in[8];
    const float* lin_W    = (const float*)d_in[9];
    const float* lin_b    = (const float*)d_in[10];
    float* out = (float*)d_out;

    cudaFuncSetAttribute(enc_tc_kernel, cudaFuncAttributeMaxDynamicSharedMemorySize, E_SZ);
    cudaFuncSetAttribute(dec_tc_kernel, cudaFuncAttributeMaxDynamicSharedMemorySize, D_SZ);

    prep_kernel<<<24, 512>>>(dec_Whh, dec_Wih, lin_W, lin_b, dec_bih, dec_bhh);
    enc_tc_kernel<<<NBATCH / TB, 512, E_SZ>>>(x, enc_Whh, enc_Wih, enc_bih, enc_bhh);
    dec0_kernel<<<NBATCH / TB, 512>>>(dec_bih, dec_bhh);
    dec_tc_kernel<<<NBATCH / TB, 512, D_SZ>>>(dec_Whh, dec_bhh);
    out_mma_kernel<<<(NBATCH * T_SEQ) / 128, 256>>>(lin_W, lin_b, out);
}